// round 2
// baseline (speedup 1.0000x reference)
#include <cuda_runtime.h>

// Problem constants (fixed by setup_inputs)
#define BATCH 4
#define SEQ   2048
#define EDIM  512
#define HNUM  8
#define RNUM  16
#define DDIM  64
#define TOK   (BATCH * SEQ)      // 8192 tokens
#define ERDIM (EDIM * RNUM)      // 8192 Wv rows

// Scratch (allocation-free: __device__ globals)
__device__ float g_Q[TOK * EDIM];           // scaled query projection, (b,s,h*d)
__device__ float g_attn[TOK * HNUM * RNUM]; // softmax over rules, [token][h][r]
__device__ float g_F[TOK * EDIM];           // fuzzy FNN output in (b,h,s,d) order!

// ----------------------------------------------------------------------------
// Generic GEMM: C[m,n] = (A[m,:] . W[n,:] + bias[n]) * scale
// A: [M x 512] row-major, W: [N x 512] row-major. Block tile 64x64, BK=32,
// 256 threads, 4x4 register microtile per thread.
// ----------------------------------------------------------------------------
__global__ __launch_bounds__(256) void gemm_bias_kernel(
    const float* __restrict__ A, const float* __restrict__ W,
    const float* __restrict__ bias, float* __restrict__ C,
    int N, float scale)
{
    __shared__ float As[64][33];
    __shared__ float Ws[64][33];

    const int tid = threadIdx.x;
    const int m0  = blockIdx.y * 64;
    const int n0  = blockIdx.x * 64;
    const int tx  = tid & 15;      // 16 col-threads
    const int ty  = tid >> 4;      // 16 row-threads
    const int lr  = tid >> 2;      // load row 0..63
    const int lc  = (tid & 3) * 8; // load col {0,8,16,24}

    float acc[4][4] = {};

    for (int kt = 0; kt < EDIM; kt += 32) {
        float4 a0 = *(const float4*)(A + (size_t)(m0 + lr) * EDIM + kt + lc);
        float4 a1 = *(const float4*)(A + (size_t)(m0 + lr) * EDIM + kt + lc + 4);
        float4 w0 = *(const float4*)(W + (size_t)(n0 + lr) * EDIM + kt + lc);
        float4 w1 = *(const float4*)(W + (size_t)(n0 + lr) * EDIM + kt + lc + 4);
        As[lr][lc+0] = a0.x; As[lr][lc+1] = a0.y; As[lr][lc+2] = a0.z; As[lr][lc+3] = a0.w;
        As[lr][lc+4] = a1.x; As[lr][lc+5] = a1.y; As[lr][lc+6] = a1.z; As[lr][lc+7] = a1.w;
        Ws[lr][lc+0] = w0.x; Ws[lr][lc+1] = w0.y; Ws[lr][lc+2] = w0.z; Ws[lr][lc+3] = w0.w;
        Ws[lr][lc+4] = w1.x; Ws[lr][lc+5] = w1.y; Ws[lr][lc+6] = w1.z; Ws[lr][lc+7] = w1.w;
        __syncthreads();

        #pragma unroll
        for (int k = 0; k < 32; k++) {
            float a[4], b[4];
            #pragma unroll
            for (int i = 0; i < 4; i++) a[i] = As[ty * 4 + i][k];
            #pragma unroll
            for (int j = 0; j < 4; j++) b[j] = Ws[tx * 4 + j][k];
            #pragma unroll
            for (int i = 0; i < 4; i++)
                #pragma unroll
                for (int j = 0; j < 4; j++)
                    acc[i][j] = fmaf(a[i], b[j], acc[i][j]);
        }
        __syncthreads();
    }

    #pragma unroll
    for (int i = 0; i < 4; i++) {
        const int m = m0 + ty * 4 + i;
        #pragma unroll
        for (int j = 0; j < 4; j++) {
            const int n = n0 + tx * 4 + j;
            C[(size_t)m * N + n] = (acc[i][j] + bias[n]) * scale;
        }
    }
}

// ----------------------------------------------------------------------------
// Fuzzy attention weights: z[r] = -0.5 * mean_d ((q - rk)/rw)^2 ; softmax over r.
// One block per token, one warp per head, lanes 0..15 own one rule each.
// ----------------------------------------------------------------------------
__global__ __launch_bounds__(256) void attn_kernel(
    const float* __restrict__ rk, const float* __restrict__ rw)
{
    __shared__ float qs[EDIM];
    const int token = blockIdx.x;
    for (int i = threadIdx.x; i < EDIM; i += 256)
        qs[i] = g_Q[(size_t)token * EDIM + i];
    __syncthreads();

    const int h    = threadIdx.x >> 5;   // 8 warps = 8 heads
    const int lane = threadIdx.x & 31;
    if (lane < 16) {
        const int r = lane;
        const float* rkp = rk + (size_t)(h * RNUM + r) * DDIM;
        const float* rwp = rw + (size_t)(h * RNUM + r) * DDIM;
        float s = 0.f;
        #pragma unroll 8
        for (int d = 0; d < DDIM; d++) {
            float diff = (qs[h * DDIM + d] - rkp[d]) / rwp[d];
            s = fmaf(diff, diff, s);
        }
        float z = -0.5f * s * (1.0f / DDIM);

        // softmax over 16 lanes
        float m = z;
        #pragma unroll
        for (int o = 8; o; o >>= 1) m = fmaxf(m, __shfl_xor_sync(0x0000ffffu, m, o));
        float e = expf(z - m);
        float sum = e;
        #pragma unroll
        for (int o = 8; o; o >>= 1) sum += __shfl_xor_sync(0x0000ffffu, sum, o);
        g_attn[(size_t)token * (HNUM * RNUM) + h * RNUM + r] = e / sum;
    }
}

// ----------------------------------------------------------------------------
// Big fused GEMM: for each token and Wv-row n = (h*64+d)*16 + r:
//   c = value[token,:] . Wv[n,:]
//   F(b,h,s,d) = 0.125 * sum_r attn[token, h, r] * (c + bv[n])
// The epilogue writes g_F in (b, h, s, d) order — this matches the reference's
// transpose(0,2,1,3).reshape(B,-1,512), which does NOT restore token order.
// ----------------------------------------------------------------------------
__global__ __launch_bounds__(256) void fused_v_kernel(
    const float* __restrict__ value, const float* __restrict__ Wv,
    const float* __restrict__ bv)
{
    __shared__ float As[64][33];
    __shared__ float Ws[64][33];

    const int tid = threadIdx.x;
    const int m0  = blockIdx.y * 64;  // token base
    const int n0  = blockIdx.x * 64;  // Wv-row base (4 hd groups x 16 rules)
    const int tx  = tid & 15;
    const int ty  = tid >> 4;
    const int lr  = tid >> 2;
    const int lc  = (tid & 3) * 8;

    float acc[4][4] = {};

    for (int kt = 0; kt < EDIM; kt += 32) {
        float4 a0 = *(const float4*)(value + (size_t)(m0 + lr) * EDIM + kt + lc);
        float4 a1 = *(const float4*)(value + (size_t)(m0 + lr) * EDIM + kt + lc + 4);
        float4 w0 = *(const float4*)(Wv    + (size_t)(n0 + lr) * EDIM + kt + lc);
        float4 w1 = *(const float4*)(Wv    + (size_t)(n0 + lr) * EDIM + kt + lc + 4);
        As[lr][lc+0] = a0.x; As[lr][lc+1] = a0.y; As[lr][lc+2] = a0.z; As[lr][lc+3] = a0.w;
        As[lr][lc+4] = a1.x; As[lr][lc+5] = a1.y; As[lr][lc+6] = a1.z; As[lr][lc+7] = a1.w;
        Ws[lr][lc+0] = w0.x; Ws[lr][lc+1] = w0.y; Ws[lr][lc+2] = w0.z; Ws[lr][lc+3] = w0.w;
        Ws[lr][lc+4] = w1.x; Ws[lr][lc+5] = w1.y; Ws[lr][lc+6] = w1.z; Ws[lr][lc+7] = w1.w;
        __syncthreads();

        #pragma unroll
        for (int k = 0; k < 32; k++) {
            float a[4], b[4];
            #pragma unroll
            for (int i = 0; i < 4; i++) a[i] = As[ty * 4 + i][k];
            #pragma unroll
            for (int j = 0; j < 4; j++) b[j] = Ws[tx * 4 + j][k];
            #pragma unroll
            for (int i = 0; i < 4; i++)
                #pragma unroll
                for (int j = 0; j < 4; j++)
                    acc[i][j] = fmaf(a[i], b[j], acc[i][j]);
        }
        __syncthreads();
    }

    // Epilogue: cols tx*4..tx*4+3 all lie in one rule-group (hd constant).
    const int hd    = (n0 + tx * 4) >> 4;  // feature index h*64+d
    const int h     = hd >> 6;
    const int d     = hd & 63;
    const int rbase = (tx * 4) & 15;       // {0,4,8,12}

    #pragma unroll
    for (int i = 0; i < 4; i++) {
        const int token = m0 + ty * 4 + i;
        const float* at = g_attn + (size_t)token * (HNUM * RNUM) + h * RNUM;
        float p = 0.f;
        #pragma unroll
        for (int j = 0; j < 4; j++) {
            const int n = n0 + tx * 4 + j;
            p = fmaf(acc[i][j] + bv[n], at[rbase + j], p);
        }
        p *= 0.125f;  // D^-0.5
        // reduce the 4 partial sums (lanes 4a..4a+3 hold the same (token,hd))
        p += __shfl_down_sync(0xffffffffu, p, 2);
        p += __shfl_down_sync(0xffffffffu, p, 1);
        if ((tx & 3) == 0) {
            const int b = token >> 11;        // token / SEQ
            const int s = token & 2047;       // token % SEQ
            // (b, h, s, d) layout
            g_F[(((size_t)b * HNUM + h) * SEQ + s) * DDIM + d] = p;
        }
    }
}

// ----------------------------------------------------------------------------
extern "C" void kernel_launch(void* const* d_in, const int* in_sizes, int n_in,
                              void* d_out, int out_size)
{
    const float* query = (const float*)d_in[0];
    // d_in[1] = key: unused by the reference computation
    const float* value = (const float*)d_in[2];
    const float* Wq    = (const float*)d_in[3];
    const float* bq    = (const float*)d_in[4];
    const float* Wv    = (const float*)d_in[5];
    const float* bv    = (const float*)d_in[6];
    const float* Wo    = (const float*)d_in[7];
    const float* bo    = (const float*)d_in[8];
    const float* rk    = (const float*)d_in[9];
    const float* rw    = (const float*)d_in[10];
    float* out = (float*)d_out;

    float *Qp = nullptr, *Fp = nullptr;
    cudaGetSymbolAddress((void**)&Qp, g_Q);
    cudaGetSymbolAddress((void**)&Fp, g_F);

    dim3 blk(256);

    // K1: q projection (scaled)
    gemm_bias_kernel<<<dim3(EDIM / 64, TOK / 64), blk>>>(
        query, Wq, bq, Qp, EDIM, 0.125f);

    // K2: fuzzy rule attention (softmax over rules)
    attn_kernel<<<dim3(TOK), blk>>>(rk, rw);

    // K3: big fused v-GEMM + attn-weighted rule reduction
    fused_v_kernel<<<dim3(ERDIM / 64, TOK / 64), blk>>>(value, Wv, bv);

    // K4: output projection (g_F rows are already in the reference's
    // post-reshape order: (b, h, s, d) flattened to 8192 x 512)
    gemm_bias_kernel<<<dim3(EDIM / 64, TOK / 64), blk>>>(
        Fp, Wo, bo, out, EDIM, 1.0f);
}

// round 4
// speedup vs baseline: 1.6973x; 1.6973x over previous
#include <cuda_runtime.h>
#include <cuda_bf16.h>
#include <cstdint>

// Problem constants (fixed by setup_inputs)
#define BATCH 4
#define SEQ   2048
#define EDIM  512
#define HNUM  8
#define RNUM  16
#define DDIM  64
#define TOK   (BATCH * SEQ)      // 8192 tokens
#define ERDIM (EDIM * RNUM)      // 8192 Wv rows
#define KBIG  1536               // 3 x 512 (hi|hi|lo vs hi|lo|hi split)
#define BKC   32                 // k-chunk (bf16 elems)
#define NCHUNK (KBIG / BKC)      // 48
#define ROWB  80                 // smem row pitch in bytes (64 data + 16 pad)
#define TILEB (128 * ROWB)       // 10240 bytes per 128x32 bf16 tile

// Scratch (allocation-free: __device__ globals)
__device__ float g_Q[TOK * EDIM];              // scaled query projection
__device__ float g_attn[TOK * HNUM * RNUM];    // softmax over rules
__device__ float g_F[TOK * EDIM];              // fuzzy output, (b,h,s,d) order
__device__ __nv_bfloat16 g_Abig[(size_t)TOK   * KBIG];  // value split [hi|hi|lo]
__device__ __nv_bfloat16 g_Bbig[(size_t)ERDIM * KBIG];  // Wv    split [hi|lo|hi]

// ---------------------------------------------------------------------------
// Portable PTX helpers (sm_80+; assemble fine for plain sm_103 target)
// ---------------------------------------------------------------------------
__device__ __forceinline__ uint32_t smem_u32(const void* p) {
    uint32_t a;
    asm("{ .reg .u64 t; cvta.to.shared.u64 t, %1; cvt.u32.u64 %0, t; }"
        : "=r"(a) : "l"(p));
    return a;
}
__device__ __forceinline__ void cp_async16(uint32_t dst, const void* src) {
    asm volatile("cp.async.cg.shared.global [%0], [%1], 16;"
                 :: "r"(dst), "l"(src) : "memory");
}
__device__ __forceinline__ void ldmatrix_x4(uint32_t* r, uint32_t addr) {
    asm volatile("ldmatrix.sync.aligned.m8n8.x4.shared.b16 {%0,%1,%2,%3}, [%4];"
                 : "=r"(r[0]), "=r"(r[1]), "=r"(r[2]), "=r"(r[3]) : "r"(addr));
}
__device__ __forceinline__ void mma_bf16(float* c, const uint32_t* a,
                                         uint32_t b0, uint32_t b1) {
    asm volatile(
        "mma.sync.aligned.m16n8k16.row.col.f32.bf16.bf16.f32 "
        "{%0,%1,%2,%3}, {%4,%5,%6,%7}, {%8,%9}, {%0,%1,%2,%3};"
        : "+f"(c[0]), "+f"(c[1]), "+f"(c[2]), "+f"(c[3])
        : "r"(a[0]), "r"(a[1]), "r"(a[2]), "r"(a[3]), "r"(b0), "r"(b1));
}

// ---------------------------------------------------------------------------
// hi/lo bf16 split conversion. mode 0 (A=value): [hi | hi | lo]
//                              mode 1 (B=Wv):    [hi | lo | hi]
// ---------------------------------------------------------------------------
template <int MODE>
__global__ __launch_bounds__(256) void split_kernel(
    const float* __restrict__ src, __nv_bfloat16* __restrict__ dst)
{
    size_t i = (size_t)blockIdx.x * 256 + threadIdx.x; // over rows*512
    int row = (int)(i >> 9);
    int k   = (int)(i & 511);
    float v = src[i];
    __nv_bfloat16 hi = __float2bfloat16(v);
    __nv_bfloat16 lo = __float2bfloat16(v - __bfloat162float(hi));
    __nv_bfloat16* d = dst + (size_t)row * KBIG;
    d[k] = hi;
    if (MODE == 0) { d[512 + k] = hi; d[1024 + k] = lo; }
    else           { d[512 + k] = lo; d[1024 + k] = hi; }
}

// ---------------------------------------------------------------------------
// fp32 SIMT GEMM (K1/K4): C[m,n] = (A[m,:].W[n,:] + bias[n]) * scale
// ---------------------------------------------------------------------------
__global__ __launch_bounds__(256) void gemm_bias_kernel(
    const float* __restrict__ A, const float* __restrict__ W,
    const float* __restrict__ bias, float* __restrict__ C,
    int N, float scale)
{
    __shared__ float As[64][33];
    __shared__ float Ws[64][33];

    const int tid = threadIdx.x;
    const int m0  = blockIdx.y * 64;
    const int n0  = blockIdx.x * 64;
    const int tx  = tid & 15;
    const int ty  = tid >> 4;
    const int lr  = tid >> 2;
    const int lc  = (tid & 3) * 8;

    float acc[4][4] = {};

    for (int kt = 0; kt < EDIM; kt += 32) {
        float4 a0 = *(const float4*)(A + (size_t)(m0 + lr) * EDIM + kt + lc);
        float4 a1 = *(const float4*)(A + (size_t)(m0 + lr) * EDIM + kt + lc + 4);
        float4 w0 = *(const float4*)(W + (size_t)(n0 + lr) * EDIM + kt + lc);
        float4 w1 = *(const float4*)(W + (size_t)(n0 + lr) * EDIM + kt + lc + 4);
        As[lr][lc+0] = a0.x; As[lr][lc+1] = a0.y; As[lr][lc+2] = a0.z; As[lr][lc+3] = a0.w;
        As[lr][lc+4] = a1.x; As[lr][lc+5] = a1.y; As[lr][lc+6] = a1.z; As[lr][lc+7] = a1.w;
        Ws[lr][lc+0] = w0.x; Ws[lr][lc+1] = w0.y; Ws[lr][lc+2] = w0.z; Ws[lr][lc+3] = w0.w;
        Ws[lr][lc+4] = w1.x; Ws[lr][lc+5] = w1.y; Ws[lr][lc+6] = w1.z; Ws[lr][lc+7] = w1.w;
        __syncthreads();

        #pragma unroll
        for (int k = 0; k < 32; k++) {
            float a[4], b[4];
            #pragma unroll
            for (int i = 0; i < 4; i++) a[i] = As[ty * 4 + i][k];
            #pragma unroll
            for (int j = 0; j < 4; j++) b[j] = Ws[tx * 4 + j][k];
            #pragma unroll
            for (int i = 0; i < 4; i++)
                #pragma unroll
                for (int j = 0; j < 4; j++)
                    acc[i][j] = fmaf(a[i], b[j], acc[i][j]);
        }
        __syncthreads();
    }

    #pragma unroll
    for (int i = 0; i < 4; i++) {
        const int m = m0 + ty * 4 + i;
        #pragma unroll
        for (int j = 0; j < 4; j++) {
            const int n = n0 + tx * 4 + j;
            C[(size_t)m * N + n] = (acc[i][j] + bias[n]) * scale;
        }
    }
}

// ---------------------------------------------------------------------------
// K2: fuzzy rule attention (softmax over rules)
// ---------------------------------------------------------------------------
__global__ __launch_bounds__(256) void attn_kernel(
    const float* __restrict__ rk, const float* __restrict__ rw)
{
    __shared__ float qs[EDIM];
    const int token = blockIdx.x;
    for (int i = threadIdx.x; i < EDIM; i += 256)
        qs[i] = g_Q[(size_t)token * EDIM + i];
    __syncthreads();

    const int h    = threadIdx.x >> 5;
    const int lane = threadIdx.x & 31;
    if (lane < 16) {
        const int r = lane;
        const float* rkp = rk + (size_t)(h * RNUM + r) * DDIM;
        const float* rwp = rw + (size_t)(h * RNUM + r) * DDIM;
        float s = 0.f;
        #pragma unroll 8
        for (int d = 0; d < DDIM; d++) {
            float diff = (qs[h * DDIM + d] - rkp[d]) / rwp[d];
            s = fmaf(diff, diff, s);
        }
        float z = -0.5f * s * (1.0f / DDIM);
        float m = z;
        #pragma unroll
        for (int o = 8; o; o >>= 1) m = fmaxf(m, __shfl_xor_sync(0x0000ffffu, m, o));
        float e = expf(z - m);
        float sum = e;
        #pragma unroll
        for (int o = 8; o; o >>= 1) sum += __shfl_xor_sync(0x0000ffffu, sum, o);
        g_attn[(size_t)token * (HNUM * RNUM) + h * RNUM + r] = e / sum;
    }
}

// ---------------------------------------------------------------------------
// K3: HMMA bf16 split-GEMM, CTA tile 128x128, BK=32, double-buffered cp.async.
//   acc[token, n] = value[token,:].Wv[n,:]  (fp32-accurate via hi/lo split)
//   F(b,h,s,d)    = 0.125 * sum_r attn[token,h,r] * (acc + bv[n]),  n=(h*64+d)*16+r
// Warp grid 2(M) x 4(N): each warp owns 64x32 via m16n8k16 tiles.
// ---------------------------------------------------------------------------
__global__ __launch_bounds__(256) void hmma_fused_v_kernel(const float* __restrict__ bv)
{
    __shared__ __align__(16) char smem[4 * TILEB];   // A0 A1 B0 B1 = 40KB
    const uint32_t sbase = smem_u32(smem);

    const int tid    = threadIdx.x;
    const int wid    = tid >> 5;
    const int lane   = tid & 31;
    const int warp_m = wid & 1;     // 0..1 -> 64-row half
    const int warp_n = wid >> 1;    // 0..3 -> 32-col quarter
    const int m0     = blockIdx.y * 128;   // token base
    const int n0     = blockIdx.x * 128;   // Wv-row base

    const __nv_bfloat16* __restrict__ Abig = g_Abig;
    const __nv_bfloat16* __restrict__ Bbig = g_Bbig;

    // per-thread load slots: idx = tid + t*256 -> row = idx>>2, 16B col = idx&3
    const int lrow = tid >> 2;
    const int lc16 = tid & 3;

    float acc[4][4][4] = {};   // [mt][nt][d0..d3]

    // -------- async load of chunk c into buffer buf --------
    auto load_chunk = [&](int c, int buf) {
        const uint32_t a_s = sbase + (uint32_t)buf * TILEB;
        const uint32_t b_s = sbase + 2u * TILEB + (uint32_t)buf * TILEB;
        #pragma unroll
        for (int t = 0; t < 2; t++) {
            const int row = lrow + t * 64;
            const uint32_t so = (uint32_t)row * ROWB + (uint32_t)lc16 * 16;
            cp_async16(a_s + so, Abig + (size_t)(m0 + row) * KBIG + c * BKC + lc16 * 8);
            cp_async16(b_s + so, Bbig + (size_t)(n0 + row) * KBIG + c * BKC + lc16 * 8);
        }
        asm volatile("cp.async.commit_group;" ::: "memory");
    };

    // ldmatrix lane addressing: row-in-16 = lane%16, k-half(16B) = lane/16
    const uint32_t lm_row = (uint32_t)(lane & 15);
    const uint32_t lm_kb  = (uint32_t)(lane >> 4) * 16;

    load_chunk(0, 0);

    for (int c = 0; c < NCHUNK; c++) {
        const int buf = c & 1;
        if (c + 1 < NCHUNK) {
            load_chunk(c + 1, buf ^ 1);
            asm volatile("cp.async.wait_group 1;" ::: "memory");
        } else {
            asm volatile("cp.async.wait_group 0;" ::: "memory");
        }
        __syncthreads();

        const uint32_t a_s = sbase + (uint32_t)buf * TILEB;
        const uint32_t b_s = sbase + 2u * TILEB + (uint32_t)buf * TILEB;

        #pragma unroll
        for (int ks = 0; ks < 2; ks++) {         // two K=16 steps per chunk
            const uint32_t kb = (uint32_t)ks * 32 + lm_kb;
            uint32_t afr[4][4];
            #pragma unroll
            for (int mt = 0; mt < 4; mt++) {
                const uint32_t row = (uint32_t)(warp_m * 64 + mt * 16) + lm_row;
                ldmatrix_x4(afr[mt], a_s + row * ROWB + kb);
            }
            uint32_t bfr[2][4];
            #pragma unroll
            for (int np = 0; np < 2; np++) {
                const uint32_t row = (uint32_t)(warp_n * 32 + np * 16) + lm_row;
                ldmatrix_x4(bfr[np], b_s + row * ROWB + kb);
            }
            #pragma unroll
            for (int mt = 0; mt < 4; mt++)
                #pragma unroll
                for (int nt = 0; nt < 4; nt++)
                    mma_bf16(acc[mt][nt], afr[mt],
                             bfr[nt >> 1][nt & 1], bfr[nt >> 1][(nt & 1) + 2]);
        }
        __syncthreads();
    }

    // -------- fused fuzzy epilogue --------
    const int q   = lane & 3;     // quad column
    const int rg  = lane >> 2;    // row-in-8
    const int hd0 = n0 >> 4;      // first feature index of this tile (mult of 8)
    const int h   = hd0 >> 6;
    const int d0c = hd0 & 63;

    // bias values this thread touches: [g][ntl*2+j]
    float bvv[2][4];
    #pragma unroll
    for (int g = 0; g < 2; g++)
        #pragma unroll
        for (int ntl = 0; ntl < 2; ntl++)
            #pragma unroll
            for (int j = 0; j < 2; j++)
                bvv[g][ntl * 2 + j] =
                    __ldg(bv + n0 + warp_n * 32 + g * 16 + ntl * 8 + q * 2 + j);

    #pragma unroll
    for (int mt = 0; mt < 4; mt++) {
        #pragma unroll
        for (int half = 0; half < 2; half++) {
            const int row   = warp_m * 64 + mt * 16 + rg + half * 8;
            const int token = m0 + row;
            const int b     = token >> 11;
            const int s     = token & 2047;
            const float* ap = g_attn + (size_t)token * (HNUM * RNUM) + h * RNUM;
            // attn at r = ntl*8 + q*2 + j
            const float at0 = ap[q * 2],     at1 = ap[q * 2 + 1];
            const float at2 = ap[q * 2 + 8], at3 = ap[q * 2 + 9];
            float* fout = g_F + (((size_t)b * HNUM + h) * SEQ + s) * DDIM;

            #pragma unroll
            for (int g = 0; g < 2; g++) {
                float p = (acc[mt][g * 2 + 0][half * 2 + 0] + bvv[g][0]) * at0
                        + (acc[mt][g * 2 + 0][half * 2 + 1] + bvv[g][1]) * at1
                        + (acc[mt][g * 2 + 1][half * 2 + 0] + bvv[g][2]) * at2
                        + (acc[mt][g * 2 + 1][half * 2 + 1] + bvv[g][3]) * at3;
                p += __shfl_down_sync(0xffffffffu, p, 2);
                p += __shfl_down_sync(0xffffffffu, p, 1);
                if (q == 0)
                    fout[d0c + warp_n * 2 + g] = p * 0.125f;
            }
        }
    }
}

// ---------------------------------------------------------------------------
extern "C" void kernel_launch(void* const* d_in, const int* in_sizes, int n_in,
                              void* d_out, int out_size)
{
    const float* query = (const float*)d_in[0];
    // d_in[1] = key: unused by the reference computation
    const float* value = (const float*)d_in[2];
    const float* Wq    = (const float*)d_in[3];
    const float* bq    = (const float*)d_in[4];
    const float* Wv    = (const float*)d_in[5];
    const float* bv    = (const float*)d_in[6];
    const float* Wo    = (const float*)d_in[7];
    const float* bo    = (const float*)d_in[8];
    const float* rk    = (const float*)d_in[9];
    const float* rw    = (const float*)d_in[10];
    float* out = (float*)d_out;

    float *Qp = nullptr, *Fp = nullptr;
    __nv_bfloat16 *Ap = nullptr, *Bp = nullptr;
    cudaGetSymbolAddress((void**)&Qp, g_Q);
    cudaGetSymbolAddress((void**)&Fp, g_F);
    cudaGetSymbolAddress((void**)&Ap, g_Abig);
    cudaGetSymbolAddress((void**)&Bp, g_Bbig);

    dim3 blk(256);

    // hi/lo bf16 splits for the big GEMM operands
    split_kernel<0><<<dim3((TOK   * EDIM) / 256), blk>>>(value, Ap);
    split_kernel<1><<<dim3((ERDIM * EDIM) / 256), blk>>>(Wv, Bp);

    // K1: q projection (scaled)
    gemm_bias_kernel<<<dim3(EDIM / 64, TOK / 64), blk>>>(query, Wq, bq, Qp, EDIM, 0.125f);

    // K2: fuzzy rule attention
    attn_kernel<<<dim3(TOK), blk>>>(rk, rw);

    // K3: tensor-core (HMMA) fused v-GEMM + rule reduction, (b,h,s,d) output
    hmma_fused_v_kernel<<<dim3(ERDIM / 128, TOK / 128), blk>>>(bv);

    // K4: output projection
    gemm_bias_kernel<<<dim3(EDIM / 64, TOK / 64), blk>>>(Fp, Wo, bo, out, EDIM, 1.0f);
}

// round 5
// speedup vs baseline: 2.5037x; 1.4751x over previous
#include <cuda_runtime.h>
#include <cuda_bf16.h>
#include <cstdint>

// Problem constants (fixed by setup_inputs)
#define BATCH 4
#define SEQ   2048
#define EDIM  512
#define HNUM  8
#define RNUM  16
#define DDIM  64
#define TOK   (BATCH * SEQ)      // 8192 tokens
#define ERDIM (EDIM * RNUM)      // 8192 Wv rows
#define KBIG  1536               // 3 x 512 (hi|hi|lo vs hi|lo|hi split)
#define BKC   32                 // k-chunk (bf16 elems)
#define NCHUNK (KBIG / BKC)      // 48
#define ROWB  80                 // smem row pitch in bytes (64 data + 16 pad)
#define TILEB (128 * ROWB)       // 10240 bytes per 128x32 bf16 tile

// Scratch (allocation-free: __device__ globals)
__device__ float g_Q[TOK * EDIM];              // scaled query projection (fp32, attn input)
__device__ float g_attn[TOK * HNUM * RNUM];    // softmax over rules
__device__ float g_iw2[HNUM * RNUM * DDIM];    // 1 / rules_widths^2
__device__ __nv_bfloat16 g_Abig[(size_t)TOK   * KBIG];  // value  split [hi|hi|lo]
__device__ __nv_bfloat16 g_Bbig[(size_t)ERDIM * KBIG];  // Wv     split [hi|lo|hi]
__device__ __nv_bfloat16 g_QSbig[(size_t)TOK  * KBIG];  // query  split [hi|hi|lo]
__device__ __nv_bfloat16 g_WqB[(size_t)EDIM   * KBIG];  // Wq     split [hi|lo|hi]
__device__ __nv_bfloat16 g_WoB[(size_t)EDIM   * KBIG];  // Wo     split [hi|lo|hi]
__device__ __nv_bfloat16 g_Fbig[(size_t)TOK   * KBIG];  // F      split [hi|hi|lo], (b,h,s,d) row order

// ---------------------------------------------------------------------------
// Portable PTX helpers (sm_80+; assemble fine for plain sm_103 target)
// ---------------------------------------------------------------------------
__device__ __forceinline__ uint32_t smem_u32(const void* p) {
    uint32_t a;
    asm("{ .reg .u64 t; cvta.to.shared.u64 t, %1; cvt.u32.u64 %0, t; }"
        : "=r"(a) : "l"(p));
    return a;
}
__device__ __forceinline__ void cp_async16(uint32_t dst, const void* src) {
    asm volatile("cp.async.cg.shared.global [%0], [%1], 16;"
                 :: "r"(dst), "l"(src) : "memory");
}
__device__ __forceinline__ void ldmatrix_x4(uint32_t* r, uint32_t addr) {
    asm volatile("ldmatrix.sync.aligned.m8n8.x4.shared.b16 {%0,%1,%2,%3}, [%4];"
                 : "=r"(r[0]), "=r"(r[1]), "=r"(r[2]), "=r"(r[3]) : "r"(addr));
}
__device__ __forceinline__ void mma_bf16(float* c, const uint32_t* a,
                                         uint32_t b0, uint32_t b1) {
    asm volatile(
        "mma.sync.aligned.m16n8k16.row.col.f32.bf16.bf16.f32 "
        "{%0,%1,%2,%3}, {%4,%5,%6,%7}, {%8,%9}, {%0,%1,%2,%3};"
        : "+f"(c[0]), "+f"(c[1]), "+f"(c[2]), "+f"(c[3])
        : "r"(a[0]), "r"(a[1]), "r"(a[2]), "r"(a[3]), "r"(b0), "r"(b1));
}

// ---------------------------------------------------------------------------
// hi/lo bf16 split conversion. mode 0 (A side): [hi | hi | lo]
//                              mode 1 (B side): [hi | lo | hi]
// ---------------------------------------------------------------------------
template <int MODE>
__global__ __launch_bounds__(256) void split_kernel(
    const float* __restrict__ src, __nv_bfloat16* __restrict__ dst)
{
    size_t i = (size_t)blockIdx.x * 256 + threadIdx.x; // over rows*512
    int row = (int)(i >> 9);
    int k   = (int)(i & 511);
    float v = src[i];
    __nv_bfloat16 hi = __float2bfloat16(v);
    __nv_bfloat16 lo = __float2bfloat16(v - __bfloat162float(hi));
    __nv_bfloat16* d = dst + (size_t)row * KBIG;
    d[k] = hi;
    if (MODE == 0) { d[512 + k] = hi; d[1024 + k] = lo; }
    else           { d[512 + k] = lo; d[1024 + k] = hi; }
}

// ---------------------------------------------------------------------------
// Rule width preprocessing: g_iw2 = 1 / rw^2 (8K elements)
// ---------------------------------------------------------------------------
__global__ __launch_bounds__(256) void prep_iw2_kernel(const float* __restrict__ rw)
{
    int i = blockIdx.x * 256 + threadIdx.x;
    if (i < HNUM * RNUM * DDIM) {
        float t = 1.0f / rw[i];
        g_iw2[i] = t * t;
    }
}

// ---------------------------------------------------------------------------
// K2: fuzzy rule attention. One warp per (token, head); all 32 lanes active.
//   z[r] = -0.5/64 * sum_d (q[d]-rk[r][d])^2 * iw2[r][d];  softmax over r.
// ---------------------------------------------------------------------------
__global__ __launch_bounds__(256) void attn_kernel(const float* __restrict__ rk)
{
    __shared__ float qs[EDIM];
    const int token = blockIdx.x;
    {
        const float4* src = (const float4*)(g_Q + (size_t)token * EDIM);
        float4* dst = (float4*)qs;
        if (threadIdx.x < 128) dst[threadIdx.x] = src[threadIdx.x];
    }
    __syncthreads();

    const int h    = threadIdx.x >> 5;   // 8 warps = 8 heads
    const int lane = threadIdx.x & 31;

    const float qa = qs[h * DDIM + lane];
    const float qb = qs[h * DDIM + lane + 32];

    float z = 0.f;
    #pragma unroll
    for (int r = 0; r < RNUM; r++) {
        const float* rp = rk    + (size_t)(h * RNUM + r) * DDIM;
        const float* wp = g_iw2 + (size_t)(h * RNUM + r) * DDIM;
        float d0 = qa - rp[lane];
        float d1 = qb - rp[lane + 32];
        float s  = d0 * d0 * wp[lane] + d1 * d1 * wp[lane + 32];
        #pragma unroll
        for (int o = 16; o; o >>= 1) s += __shfl_xor_sync(0xffffffffu, s, o);
        if (lane == r) z = s;
    }

    if (lane < 16) {
        z *= -0.5f / DDIM;
        float m = z;
        #pragma unroll
        for (int o = 8; o; o >>= 1) m = fmaxf(m, __shfl_xor_sync(0x0000ffffu, m, o));
        float e = expf(z - m);
        float sum = e;
        #pragma unroll
        for (int o = 8; o; o >>= 1) sum += __shfl_xor_sync(0x0000ffffu, sum, o);
        g_attn[(size_t)token * (HNUM * RNUM) + h * RNUM + lane] = e / sum;
    }
}

// ---------------------------------------------------------------------------
// Generic HMMA split-GEMM (K1/K4): C[m,n] = (A[m,:].B[n,:] + bias[n]) * scale
// A: [M x 1536] bf16 [hi|hi|lo], B: [512 x 1536] bf16 [hi|lo|hi], C fp32 [M x 512].
// CTA tile 128x128, BK=32, double-buffered cp.async; warps 2(M) x 4(N).
// ---------------------------------------------------------------------------
__global__ __launch_bounds__(256) void hmma_gemm_bias_kernel(
    const __nv_bfloat16* __restrict__ A, const __nv_bfloat16* __restrict__ B,
    const float* __restrict__ bias, float* __restrict__ C, float scale)
{
    __shared__ __align__(16) char smem[4 * TILEB];   // A0 A1 B0 B1 = 40KB
    const uint32_t sbase = smem_u32(smem);

    const int tid    = threadIdx.x;
    const int lane   = tid & 31;
    const int wid    = tid >> 5;
    const int warp_m = wid & 1;
    const int warp_n = wid >> 1;
    const int m0     = blockIdx.y * 128;
    const int n0     = blockIdx.x * 128;

    const int lrow = tid >> 2;
    const int lc16 = tid & 3;

    float acc[4][4][4] = {};

    auto load_chunk = [&](int c, int buf) {
        const uint32_t a_s = sbase + (uint32_t)buf * TILEB;
        const uint32_t b_s = sbase + 2u * TILEB + (uint32_t)buf * TILEB;
        #pragma unroll
        for (int t = 0; t < 2; t++) {
            const int row = lrow + t * 64;
            const uint32_t so = (uint32_t)row * ROWB + (uint32_t)lc16 * 16;
            cp_async16(a_s + so, A + (size_t)(m0 + row) * KBIG + c * BKC + lc16 * 8);
            cp_async16(b_s + so, B + (size_t)(n0 + row) * KBIG + c * BKC + lc16 * 8);
        }
        asm volatile("cp.async.commit_group;" ::: "memory");
    };

    const uint32_t lm_row = (uint32_t)(lane & 15);
    const uint32_t lm_kb  = (uint32_t)(lane >> 4) * 16;

    load_chunk(0, 0);

    for (int c = 0; c < NCHUNK; c++) {
        const int buf = c & 1;
        if (c + 1 < NCHUNK) {
            load_chunk(c + 1, buf ^ 1);
            asm volatile("cp.async.wait_group 1;" ::: "memory");
        } else {
            asm volatile("cp.async.wait_group 0;" ::: "memory");
        }
        __syncthreads();

        const uint32_t a_s = sbase + (uint32_t)buf * TILEB;
        const uint32_t b_s = sbase + 2u * TILEB + (uint32_t)buf * TILEB;

        #pragma unroll
        for (int ks = 0; ks < 2; ks++) {
            const uint32_t kb = (uint32_t)ks * 32 + lm_kb;
            uint32_t afr[4][4];
            #pragma unroll
            for (int mt = 0; mt < 4; mt++) {
                const uint32_t row = (uint32_t)(warp_m * 64 + mt * 16) + lm_row;
                ldmatrix_x4(afr[mt], a_s + row * ROWB + kb);
            }
            uint32_t bfr[2][4];
            #pragma unroll
            for (int np = 0; np < 2; np++) {
                const uint32_t row = (uint32_t)(warp_n * 32 + np * 16) + lm_row;
                ldmatrix_x4(bfr[np], b_s + row * ROWB + kb);
            }
            #pragma unroll
            for (int mt = 0; mt < 4; mt++)
                #pragma unroll
                for (int nt = 0; nt < 4; nt++)
                    mma_bf16(acc[mt][nt], afr[mt],
                             bfr[nt >> 1][nt & 1], bfr[nt >> 1][(nt & 1) + 2]);
        }
        __syncthreads();
    }

    // Plain bias+scale epilogue
    const int q  = lane & 3;
    const int rg = lane >> 2;
    #pragma unroll
    for (int mt = 0; mt < 4; mt++) {
        #pragma unroll
        for (int half = 0; half < 2; half++) {
            const int row = m0 + warp_m * 64 + mt * 16 + rg + half * 8;
            #pragma unroll
            for (int nt = 0; nt < 4; nt++) {
                const int col = n0 + warp_n * 32 + nt * 8 + q * 2;
                float2 v;
                v.x = (acc[mt][nt][half * 2 + 0] + bias[col])     * scale;
                v.y = (acc[mt][nt][half * 2 + 1] + bias[col + 1]) * scale;
                *(float2*)(C + (size_t)row * EDIM + col) = v;
            }
        }
    }
}

// ---------------------------------------------------------------------------
// K3: HMMA bf16 split-GEMM + fused fuzzy epilogue. Writes g_Fbig ([hi|hi|lo])
// directly in the reference's post-transpose (b,h,s,d) row order.
// ---------------------------------------------------------------------------
__global__ __launch_bounds__(256) void hmma_fused_v_kernel(const float* __restrict__ bv)
{
    __shared__ __align__(16) char smem[4 * TILEB];   // 40KB
    const uint32_t sbase = smem_u32(smem);

    const int tid    = threadIdx.x;
    const int lane   = tid & 31;
    const int wid    = tid >> 5;
    const int warp_m = wid & 1;
    const int warp_n = wid >> 1;
    const int m0     = blockIdx.y * 128;   // token base
    const int n0     = blockIdx.x * 128;   // Wv-row base

    const __nv_bfloat16* __restrict__ Abig = g_Abig;
    const __nv_bfloat16* __restrict__ Bbig = g_Bbig;

    const int lrow = tid >> 2;
    const int lc16 = tid & 3;

    float acc[4][4][4] = {};

    auto load_chunk = [&](int c, int buf) {
        const uint32_t a_s = sbase + (uint32_t)buf * TILEB;
        const uint32_t b_s = sbase + 2u * TILEB + (uint32_t)buf * TILEB;
        #pragma unroll
        for (int t = 0; t < 2; t++) {
            const int row = lrow + t * 64;
            const uint32_t so = (uint32_t)row * ROWB + (uint32_t)lc16 * 16;
            cp_async16(a_s + so, Abig + (size_t)(m0 + row) * KBIG + c * BKC + lc16 * 8);
            cp_async16(b_s + so, Bbig + (size_t)(n0 + row) * KBIG + c * BKC + lc16 * 8);
        }
        asm volatile("cp.async.commit_group;" ::: "memory");
    };

    const uint32_t lm_row = (uint32_t)(lane & 15);
    const uint32_t lm_kb  = (uint32_t)(lane >> 4) * 16;

    load_chunk(0, 0);

    for (int c = 0; c < NCHUNK; c++) {
        const int buf = c & 1;
        if (c + 1 < NCHUNK) {
            load_chunk(c + 1, buf ^ 1);
            asm volatile("cp.async.wait_group 1;" ::: "memory");
        } else {
            asm volatile("cp.async.wait_group 0;" ::: "memory");
        }
        __syncthreads();

        const uint32_t a_s = sbase + (uint32_t)buf * TILEB;
        const uint32_t b_s = sbase + 2u * TILEB + (uint32_t)buf * TILEB;

        #pragma unroll
        for (int ks = 0; ks < 2; ks++) {
            const uint32_t kb = (uint32_t)ks * 32 + lm_kb;
            uint32_t afr[4][4];
            #pragma unroll
            for (int mt = 0; mt < 4; mt++) {
                const uint32_t row = (uint32_t)(warp_m * 64 + mt * 16) + lm_row;
                ldmatrix_x4(afr[mt], a_s + row * ROWB + kb);
            }
            uint32_t bfr[2][4];
            #pragma unroll
            for (int np = 0; np < 2; np++) {
                const uint32_t row = (uint32_t)(warp_n * 32 + np * 16) + lm_row;
                ldmatrix_x4(bfr[np], b_s + row * ROWB + kb);
            }
            #pragma unroll
            for (int mt = 0; mt < 4; mt++)
                #pragma unroll
                for (int nt = 0; nt < 4; nt++)
                    mma_bf16(acc[mt][nt], afr[mt],
                             bfr[nt >> 1][nt & 1], bfr[nt >> 1][(nt & 1) + 2]);
        }
        __syncthreads();
    }

    // -------- fused fuzzy epilogue (emits hi/lo bf16 split of F) --------
    const int q   = lane & 3;
    const int rg  = lane >> 2;
    const int hd0 = n0 >> 4;      // first feature of tile (mult of 8)
    const int h   = hd0 >> 6;
    const int d0c = hd0 & 63;

    float bvv[2][4];
    #pragma unroll
    for (int g = 0; g < 2; g++)
        #pragma unroll
        for (int ntl = 0; ntl < 2; ntl++)
            #pragma unroll
            for (int j = 0; j < 2; j++)
                bvv[g][ntl * 2 + j] =
                    __ldg(bv + n0 + warp_n * 32 + g * 16 + ntl * 8 + q * 2 + j);

    #pragma unroll
    for (int mt = 0; mt < 4; mt++) {
        #pragma unroll
        for (int half = 0; half < 2; half++) {
            const int rowm  = warp_m * 64 + mt * 16 + rg + half * 8;
            const int token = m0 + rowm;
            const int b     = token >> 11;
            const int s     = token & 2047;
            const float* ap = g_attn + (size_t)token * (HNUM * RNUM) + h * RNUM;
            const float at0 = ap[q * 2],     at1 = ap[q * 2 + 1];
            const float at2 = ap[q * 2 + 8], at3 = ap[q * 2 + 9];

            // row/col of F in the flattened (b,h,s,d) -> [8192 x 512] view
            const int frow = (b * HNUM + h) * 256 + (s >> 3);
            const int cbase = (s & 7) * 64;

            #pragma unroll
            for (int g = 0; g < 2; g++) {
                float p = (acc[mt][g * 2 + 0][half * 2 + 0] + bvv[g][0]) * at0
                        + (acc[mt][g * 2 + 0][half * 2 + 1] + bvv[g][1]) * at1
                        + (acc[mt][g * 2 + 1][half * 2 + 0] + bvv[g][2]) * at2
                        + (acc[mt][g * 2 + 1][half * 2 + 1] + bvv[g][3]) * at3;
                p += __shfl_down_sync(0xffffffffu, p, 2);
                p += __shfl_down_sync(0xffffffffu, p, 1);
                if (q == 0) {
                    p *= 0.125f;  // D^-0.5
                    const int col = cbase + d0c + warp_n * 2 + g;
                    __nv_bfloat16 hi = __float2bfloat16(p);
                    __nv_bfloat16 lo = __float2bfloat16(p - __bfloat162float(hi));
                    __nv_bfloat16* f = g_Fbig + (size_t)frow * KBIG + col;
                    f[0]    = hi;
                    f[512]  = hi;
                    f[1024] = lo;
                }
            }
        }
    }
}

// ---------------------------------------------------------------------------
extern "C" void kernel_launch(void* const* d_in, const int* in_sizes, int n_in,
                              void* d_out, int out_size)
{
    const float* query = (const float*)d_in[0];
    // d_in[1] = key: unused by the reference computation
    const float* value = (const float*)d_in[2];
    const float* Wq    = (const float*)d_in[3];
    const float* bq    = (const float*)d_in[4];
    const float* Wv    = (const float*)d_in[5];
    const float* bv    = (const float*)d_in[6];
    const float* Wo    = (const float*)d_in[7];
    const float* bo    = (const float*)d_in[8];
    const float* rk    = (const float*)d_in[9];
    const float* rw    = (const float*)d_in[10];
    float* out = (float*)d_out;

    float* Qp = nullptr;
    __nv_bfloat16 *Ap = nullptr, *Bp = nullptr, *QSp = nullptr;
    __nv_bfloat16 *WqBp = nullptr, *WoBp = nullptr, *Fp = nullptr;
    cudaGetSymbolAddress((void**)&Qp,   g_Q);
    cudaGetSymbolAddress((void**)&Ap,   g_Abig);
    cudaGetSymbolAddress((void**)&Bp,   g_Bbig);
    cudaGetSymbolAddress((void**)&QSp,  g_QSbig);
    cudaGetSymbolAddress((void**)&WqBp, g_WqB);
    cudaGetSymbolAddress((void**)&WoBp, g_WoB);
    cudaGetSymbolAddress((void**)&Fp,   g_Fbig);

    dim3 blk(256);

    // hi/lo bf16 splits
    split_kernel<0><<<dim3((TOK   * EDIM) / 256), blk>>>(value, Ap);
    split_kernel<1><<<dim3((ERDIM * EDIM) / 256), blk>>>(Wv, Bp);
    split_kernel<0><<<dim3((TOK   * EDIM) / 256), blk>>>(query, QSp);
    split_kernel<1><<<dim3((EDIM  * EDIM) / 256), blk>>>(Wq, WqBp);
    split_kernel<1><<<dim3((EDIM  * EDIM) / 256), blk>>>(Wo, WoBp);
    prep_iw2_kernel<<<dim3((HNUM * RNUM * DDIM + 255) / 256), blk>>>(rw);

    // K1: q projection (scaled) via HMMA
    hmma_gemm_bias_kernel<<<dim3(EDIM / 128, TOK / 128), blk>>>(
        QSp, WqBp, bq, Qp, 0.125f);

    // K2: fuzzy rule attention
    attn_kernel<<<dim3(TOK), blk>>>(rk);

    // K3: fused v-GEMM + rule reduction (writes g_Fbig split, (b,h,s,d) order)
    hmma_fused_v_kernel<<<dim3(ERDIM / 128, TOK / 128), blk>>>(bv);

    // K4: output projection via HMMA
    hmma_gemm_bias_kernel<<<dim3(EDIM / 128, TOK / 128), blk>>>(
        Fp, WoBp, bo, out, 1.0f);
}

// round 6
// speedup vs baseline: 2.6428x; 1.0555x over previous
#include <cuda_runtime.h>
#include <cuda_bf16.h>
#include <cstdint>

// Problem constants (fixed by setup_inputs)
#define BATCH 4
#define SEQ   2048
#define EDIM  512
#define HNUM  8
#define RNUM  16
#define DDIM  64
#define TOK   (BATCH * SEQ)      // 8192 tokens
#define ERDIM (EDIM * RNUM)      // 8192 Wv rows

// K1/K4 (old [hi|hi|lo] concat path)
#define KBIG  1536
#define BKC   32
#define NCHUNK (KBIG / BKC)      // 48
#define ROWB  80
#define TILEB (128 * ROWB)

// K3 (new [hi|lo] plane path)
#define K3_TM   256
#define K3_TN   128
#define K3_NCH  16               // 512 / 32
#define RX      144              // smem row pitch: 64B hi + 64B lo + 16B pad
#define K3_AT   (K3_TM * RX)     // 36864
#define K3_BT   (K3_TN * RX)     // 18432
#define K3_STAGE (K3_AT + K3_BT) // 55296
#define K3_SMEM (2 * K3_STAGE)   // 110592

// Scratch (allocation-free: __device__ globals)
__device__ float g_Q[TOK * EDIM];              // scaled query projection
__device__ float g_attn[TOK * HNUM * RNUM];    // softmax over rules
__device__ float g_iw2[HNUM * RNUM * DDIM];    // 1 / rules_widths^2
__device__ __nv_bfloat16 g_A2[(size_t)TOK   * 1024];  // value row: [hi(512)|lo(512)]
__device__ __nv_bfloat16 g_B2[(size_t)ERDIM * 1024];  // Wv    row: [hi(512)|lo(512)]
__device__ __nv_bfloat16 g_QSbig[(size_t)TOK * KBIG]; // query  split [hi|hi|lo]
__device__ __nv_bfloat16 g_WqB[(size_t)EDIM  * KBIG]; // Wq     split [hi|lo|hi]
__device__ __nv_bfloat16 g_WoB[(size_t)EDIM  * KBIG]; // Wo     split [hi|lo|hi]
__device__ __nv_bfloat16 g_Fbig[(size_t)TOK  * KBIG]; // F      split [hi|hi|lo], (b,h,s,d) rows

// ---------------------------------------------------------------------------
// Portable PTX helpers (sm_80+)
// ---------------------------------------------------------------------------
__device__ __forceinline__ uint32_t smem_u32(const void* p) {
    uint32_t a;
    asm("{ .reg .u64 t; cvta.to.shared.u64 t, %1; cvt.u32.u64 %0, t; }"
        : "=r"(a) : "l"(p));
    return a;
}
__device__ __forceinline__ void cp_async16(uint32_t dst, const void* src) {
    asm volatile("cp.async.cg.shared.global [%0], [%1], 16;"
                 :: "r"(dst), "l"(src) : "memory");
}
__device__ __forceinline__ void ldmatrix_x4(uint32_t* r, uint32_t addr) {
    asm volatile("ldmatrix.sync.aligned.m8n8.x4.shared.b16 {%0,%1,%2,%3}, [%4];"
                 : "=r"(r[0]), "=r"(r[1]), "=r"(r[2]), "=r"(r[3]) : "r"(addr));
}
__device__ __forceinline__ void mma_bf16(float* c, const uint32_t* a,
                                         uint32_t b0, uint32_t b1) {
    asm volatile(
        "mma.sync.aligned.m16n8k16.row.col.f32.bf16.bf16.f32 "
        "{%0,%1,%2,%3}, {%4,%5,%6,%7}, {%8,%9}, {%0,%1,%2,%3};"
        : "+f"(c[0]), "+f"(c[1]), "+f"(c[2]), "+f"(c[3])
        : "r"(a[0]), "r"(a[1]), "r"(a[2]), "r"(a[3]), "r"(b0), "r"(b1));
}

// ---------------------------------------------------------------------------
// Split kernels.
//  split_kernel<0>: [hi|hi|lo] (K'=1536, A side of K1/K4)
//  split_kernel<1>: [hi|lo|hi] (K'=1536, B side of K1/K4)
//  split2_kernel  : [hi|lo]    (K'=1024, K3 operands)
// ---------------------------------------------------------------------------
template <int MODE>
__global__ __launch_bounds__(256) void split_kernel(
    const float* __restrict__ src, __nv_bfloat16* __restrict__ dst)
{
    size_t i = (size_t)blockIdx.x * 256 + threadIdx.x;
    int row = (int)(i >> 9);
    int k   = (int)(i & 511);
    float v = src[i];
    __nv_bfloat16 hi = __float2bfloat16(v);
    __nv_bfloat16 lo = __float2bfloat16(v - __bfloat162float(hi));
    __nv_bfloat16* d = dst + (size_t)row * KBIG;
    d[k] = hi;
    if (MODE == 0) { d[512 + k] = hi; d[1024 + k] = lo; }
    else           { d[512 + k] = lo; d[1024 + k] = hi; }
}

__global__ __launch_bounds__(256) void split2_kernel(
    const float* __restrict__ src, __nv_bfloat16* __restrict__ dst)
{
    size_t i = (size_t)blockIdx.x * 256 + threadIdx.x;
    int row = (int)(i >> 9);
    int k   = (int)(i & 511);
    float v = src[i];
    __nv_bfloat16 hi = __float2bfloat16(v);
    __nv_bfloat16 lo = __float2bfloat16(v - __bfloat162float(hi));
    __nv_bfloat16* d = dst + (size_t)row * 1024;
    d[k]       = hi;
    d[512 + k] = lo;
}

// ---------------------------------------------------------------------------
__global__ __launch_bounds__(256) void prep_iw2_kernel(const float* __restrict__ rw)
{
    int i = blockIdx.x * 256 + threadIdx.x;
    if (i < HNUM * RNUM * DDIM) {
        float t = 1.0f / rw[i];
        g_iw2[i] = t * t;
    }
}

// ---------------------------------------------------------------------------
// K2: fuzzy rule attention. One warp per (token, head); all 32 lanes active.
// ---------------------------------------------------------------------------
__global__ __launch_bounds__(256) void attn_kernel(const float* __restrict__ rk)
{
    __shared__ float qs[EDIM];
    const int token = blockIdx.x;
    {
        const float4* src = (const float4*)(g_Q + (size_t)token * EDIM);
        float4* dst = (float4*)qs;
        if (threadIdx.x < 128) dst[threadIdx.x] = src[threadIdx.x];
    }
    __syncthreads();

    const int h    = threadIdx.x >> 5;
    const int lane = threadIdx.x & 31;

    const float qa = qs[h * DDIM + lane];
    const float qb = qs[h * DDIM + lane + 32];

    float z = 0.f;
    #pragma unroll
    for (int r = 0; r < RNUM; r++) {
        const float* rp = rk    + (size_t)(h * RNUM + r) * DDIM;
        const float* wp = g_iw2 + (size_t)(h * RNUM + r) * DDIM;
        float d0 = qa - rp[lane];
        float d1 = qb - rp[lane + 32];
        float s  = d0 * d0 * wp[lane] + d1 * d1 * wp[lane + 32];
        #pragma unroll
        for (int o = 16; o; o >>= 1) s += __shfl_xor_sync(0xffffffffu, s, o);
        if (lane == r) z = s;
    }

    if (lane < 16) {
        z *= -0.5f / DDIM;
        float m = z;
        #pragma unroll
        for (int o = 8; o; o >>= 1) m = fmaxf(m, __shfl_xor_sync(0x0000ffffu, m, o));
        float e = expf(z - m);
        float sum = e;
        #pragma unroll
        for (int o = 8; o; o >>= 1) sum += __shfl_xor_sync(0x0000ffffu, sum, o);
        g_attn[(size_t)token * (HNUM * RNUM) + h * RNUM + lane] = e / sum;
    }
}

// ---------------------------------------------------------------------------
// K1/K4: HMMA split-GEMM over K'=1536, tile 128x128, double-buffered.
// ---------------------------------------------------------------------------
__global__ __launch_bounds__(256) void hmma_gemm_bias_kernel(
    const __nv_bfloat16* __restrict__ A, const __nv_bfloat16* __restrict__ B,
    const float* __restrict__ bias, float* __restrict__ C, float scale)
{
    __shared__ __align__(16) char smem[4 * TILEB];
    const uint32_t sbase = smem_u32(smem);

    const int tid    = threadIdx.x;
    const int lane   = tid & 31;
    const int wid    = tid >> 5;
    const int warp_m = wid & 1;
    const int warp_n = wid >> 1;
    const int m0     = blockIdx.y * 128;
    const int n0     = blockIdx.x * 128;

    const int lrow = tid >> 2;
    const int lc16 = tid & 3;

    float acc[4][4][4] = {};

    auto load_chunk = [&](int c, int buf) {
        const uint32_t a_s = sbase + (uint32_t)buf * TILEB;
        const uint32_t b_s = sbase + 2u * TILEB + (uint32_t)buf * TILEB;
        #pragma unroll
        for (int t = 0; t < 2; t++) {
            const int row = lrow + t * 64;
            const uint32_t so = (uint32_t)row * ROWB + (uint32_t)lc16 * 16;
            cp_async16(a_s + so, A + (size_t)(m0 + row) * KBIG + c * BKC + lc16 * 8);
            cp_async16(b_s + so, B + (size_t)(n0 + row) * KBIG + c * BKC + lc16 * 8);
        }
        asm volatile("cp.async.commit_group;" ::: "memory");
    };

    const uint32_t lm_row = (uint32_t)(lane & 15);
    const uint32_t lm_kb  = (uint32_t)(lane >> 4) * 16;

    load_chunk(0, 0);

    for (int c = 0; c < NCHUNK; c++) {
        const int buf = c & 1;
        if (c + 1 < NCHUNK) {
            load_chunk(c + 1, buf ^ 1);
            asm volatile("cp.async.wait_group 1;" ::: "memory");
        } else {
            asm volatile("cp.async.wait_group 0;" ::: "memory");
        }
        __syncthreads();

        const uint32_t a_s = sbase + (uint32_t)buf * TILEB;
        const uint32_t b_s = sbase + 2u * TILEB + (uint32_t)buf * TILEB;

        #pragma unroll
        for (int ks = 0; ks < 2; ks++) {
            const uint32_t kb = (uint32_t)ks * 32 + lm_kb;
            uint32_t afr[4][4];
            #pragma unroll
            for (int mt = 0; mt < 4; mt++) {
                const uint32_t row = (uint32_t)(warp_m * 64 + mt * 16) + lm_row;
                ldmatrix_x4(afr[mt], a_s + row * ROWB + kb);
            }
            uint32_t bfr[2][4];
            #pragma unroll
            for (int np = 0; np < 2; np++) {
                const uint32_t row = (uint32_t)(warp_n * 32 + np * 16) + lm_row;
                ldmatrix_x4(bfr[np], b_s + row * ROWB + kb);
            }
            #pragma unroll
            for (int mt = 0; mt < 4; mt++)
                #pragma unroll
                for (int nt = 0; nt < 4; nt++)
                    mma_bf16(acc[mt][nt], afr[mt],
                             bfr[nt >> 1][nt & 1], bfr[nt >> 1][(nt & 1) + 2]);
        }
        __syncthreads();
    }

    const int q  = lane & 3;
    const int rg = lane >> 2;
    #pragma unroll
    for (int mt = 0; mt < 4; mt++) {
        #pragma unroll
        for (int half = 0; half < 2; half++) {
            const int row = m0 + warp_m * 64 + mt * 16 + rg + half * 8;
            #pragma unroll
            for (int nt = 0; nt < 4; nt++) {
                const int col = n0 + warp_n * 32 + nt * 8 + q * 2;
                float2 v;
                v.x = (acc[mt][nt][half * 2 + 0] + bias[col])     * scale;
                v.y = (acc[mt][nt][half * 2 + 1] + bias[col + 1]) * scale;
                *(float2*)(C + (size_t)row * EDIM + col) = v;
            }
        }
    }
}

// ---------------------------------------------------------------------------
// K3: HMMA [hi|lo]-plane split-GEMM + fused fuzzy epilogue.
//   Per 32-K chunk: load Ahi,Alo (256x32) and Bhi,Blo (128x32); compute
//   Ahi*Bhi + Ahi*Blo + Alo*Bhi  (lo*lo dropped, ~2^-18 relative).
// Tile 256x128, 512 threads (warps 4x4, 64x32 each), 2-stage cp.async,
// ONE __syncthreads per chunk. Writes g_Fbig [hi|hi|lo] in (b,h,s,d) order.
// ---------------------------------------------------------------------------
__global__ void __launch_bounds__(512, 1) hmma_fused_v2_kernel(const float* __restrict__ bv)
{
    extern __shared__ __align__(16) char smem[];
    const uint32_t sbase = smem_u32(smem);

    const int tid    = threadIdx.x;
    const int lane   = tid & 31;
    const int wid    = tid >> 5;
    const int warp_m = wid & 3;     // 4 x 64 rows
    const int warp_n = wid >> 2;    // 4 x 32 cols
    const int m0     = blockIdx.y * K3_TM;   // token base
    const int n0     = blockIdx.x * K3_TN;   // Wv-row base

    float acc[4][4][4] = {};

    // smem row layout: [hi 64B | lo 64B | pad 16B] (RX=144 -> conflict-free ldmatrix)
    auto load_chunk = [&](int c, int buf) {
        const uint32_t s0 = sbase + (uint32_t)buf * K3_STAGE;
        #pragma unroll
        for (int i = 0; i < 4; i++) {        // A: 256 rows x 8 x 16B
            const int idx  = tid + i * 512;
            const int row  = idx >> 3;
            const int half = (idx >> 2) & 1;
            const int c16  = idx & 3;
            cp_async16(s0 + (uint32_t)row * RX + (uint32_t)half * 64 + (uint32_t)c16 * 16,
                       g_A2 + (size_t)(m0 + row) * 1024 + half * 512 + c * 32 + c16 * 8);
        }
        #pragma unroll
        for (int i = 0; i < 2; i++) {        // B: 128 rows x 8 x 16B
            const int idx  = tid + i * 512;
            const int row  = idx >> 3;
            const int half = (idx >> 2) & 1;
            const int c16  = idx & 3;
            cp_async16(s0 + K3_AT + (uint32_t)row * RX + (uint32_t)half * 64 + (uint32_t)c16 * 16,
                       g_B2 + (size_t)(n0 + row) * 1024 + half * 512 + c * 32 + c16 * 8);
        }
        asm volatile("cp.async.commit_group;" ::: "memory");
    };

    const uint32_t lm_row = (uint32_t)(lane & 15);
    const uint32_t lm_kb  = (uint32_t)(lane >> 4) * 16;

    load_chunk(0, 0);

    for (int c = 0; c < K3_NCH; c++) {
        asm volatile("cp.async.wait_group 0;" ::: "memory");
        __syncthreads();
        // safe: slot (c+1)&1 was last READ in chunk c-1, which all warps
        // finished before the sync above.
        if (c + 1 < K3_NCH) load_chunk(c + 1, (c + 1) & 1);

        const uint32_t a_s = sbase + (uint32_t)(c & 1) * K3_STAGE;
        const uint32_t b_s = a_s + K3_AT;

        #pragma unroll
        for (int ks = 0; ks < 2; ks++) {
            const uint32_t kb = (uint32_t)ks * 32 + lm_kb;
            uint32_t afr[4][4];
            uint32_t bh[2][4], bl[2][4];
            #pragma unroll
            for (int mt = 0; mt < 4; mt++) {          // A hi
                const uint32_t row = (uint32_t)(warp_m * 64 + mt * 16) + lm_row;
                ldmatrix_x4(afr[mt], a_s + row * RX + kb);
            }
            #pragma unroll
            for (int np = 0; np < 2; np++) {          // B hi + B lo
                const uint32_t row = (uint32_t)(warp_n * 32 + np * 16) + lm_row;
                ldmatrix_x4(bh[np], b_s + row * RX + kb);
                ldmatrix_x4(bl[np], b_s + row * RX + kb + 64);
            }
            #pragma unroll
            for (int mt = 0; mt < 4; mt++)            // P1: hi*hi
                #pragma unroll
                for (int nt = 0; nt < 4; nt++)
                    mma_bf16(acc[mt][nt], afr[mt],
                             bh[nt >> 1][nt & 1], bh[nt >> 1][(nt & 1) + 2]);
            #pragma unroll
            for (int mt = 0; mt < 4; mt++)            // P2: hi*lo
                #pragma unroll
                for (int nt = 0; nt < 4; nt++)
                    mma_bf16(acc[mt][nt], afr[mt],
                             bl[nt >> 1][nt & 1], bl[nt >> 1][(nt & 1) + 2]);
            #pragma unroll
            for (int mt = 0; mt < 4; mt++) {          // A lo (reuse afr regs)
                const uint32_t row = (uint32_t)(warp_m * 64 + mt * 16) + lm_row;
                ldmatrix_x4(afr[mt], a_s + row * RX + kb + 64);
            }
            #pragma unroll
            for (int mt = 0; mt < 4; mt++)            // P3: lo*hi
                #pragma unroll
                for (int nt = 0; nt < 4; nt++)
                    mma_bf16(acc[mt][nt], afr[mt],
                             bh[nt >> 1][nt & 1], bh[nt >> 1][(nt & 1) + 2]);
        }
    }

    // -------- fused fuzzy epilogue (emits hi/lo bf16 split of F) --------
    const int q   = lane & 3;
    const int rg  = lane >> 2;
    const int hd0 = n0 >> 4;      // first feature of tile (multiple of 8)
    const int h   = hd0 >> 6;
    const int d0c = hd0 & 63;

    float bvv[2][4];
    #pragma unroll
    for (int g = 0; g < 2; g++)
        #pragma unroll
        for (int ntl = 0; ntl < 2; ntl++)
            #pragma unroll
            for (int j = 0; j < 2; j++)
                bvv[g][ntl * 2 + j] =
                    __ldg(bv + n0 + warp_n * 32 + g * 16 + ntl * 8 + q * 2 + j);

    #pragma unroll
    for (int mt = 0; mt < 4; mt++) {
        #pragma unroll
        for (int half = 0; half < 2; half++) {
            const int rowm  = warp_m * 64 + mt * 16 + rg + half * 8;
            const int token = m0 + rowm;
            const int b     = token >> 11;
            const int s     = token & 2047;
            const float* ap = g_attn + (size_t)token * (HNUM * RNUM) + h * RNUM;
            const float at0 = ap[q * 2],     at1 = ap[q * 2 + 1];
            const float at2 = ap[q * 2 + 8], at3 = ap[q * 2 + 9];

            const int frow  = (b * HNUM + h) * 256 + (s >> 3);
            const int cbase = (s & 7) * 64;

            #pragma unroll
            for (int g = 0; g < 2; g++) {
                float p = (acc[mt][g * 2 + 0][half * 2 + 0] + bvv[g][0]) * at0
                        + (acc[mt][g * 2 + 0][half * 2 + 1] + bvv[g][1]) * at1
                        + (acc[mt][g * 2 + 1][half * 2 + 0] + bvv[g][2]) * at2
                        + (acc[mt][g * 2 + 1][half * 2 + 1] + bvv[g][3]) * at3;
                p += __shfl_down_sync(0xffffffffu, p, 2);
                p += __shfl_down_sync(0xffffffffu, p, 1);
                if (q == 0) {
                    p *= 0.125f;  // D^-0.5
                    const int col = cbase + d0c + warp_n * 2 + g;
                    __nv_bfloat16 hi = __float2bfloat16(p);
                    __nv_bfloat16 lo = __float2bfloat16(p - __bfloat162float(hi));
                    __nv_bfloat16* f = g_Fbig + (size_t)frow * KBIG + col;
                    f[0]    = hi;
                    f[512]  = hi;
                    f[1024] = lo;
                }
            }
        }
    }
}

// ---------------------------------------------------------------------------
extern "C" void kernel_launch(void* const* d_in, const int* in_sizes, int n_in,
                              void* d_out, int out_size)
{
    const float* query = (const float*)d_in[0];
    // d_in[1] = key: unused by the reference computation
    const float* value = (const float*)d_in[2];
    const float* Wq    = (const float*)d_in[3];
    const float* bq    = (const float*)d_in[4];
    const float* Wv    = (const float*)d_in[5];
    const float* bv    = (const float*)d_in[6];
    const float* Wo    = (const float*)d_in[7];
    const float* bo    = (const float*)d_in[8];
    const float* rk    = (const float*)d_in[9];
    const float* rw    = (const float*)d_in[10];
    float* out = (float*)d_out;

    float* Qp = nullptr;
    __nv_bfloat16 *A2p = nullptr, *B2p = nullptr, *QSp = nullptr;
    __nv_bfloat16 *WqBp = nullptr, *WoBp = nullptr, *Fp = nullptr;
    cudaGetSymbolAddress((void**)&Qp,   g_Q);
    cudaGetSymbolAddress((void**)&A2p,  g_A2);
    cudaGetSymbolAddress((void**)&B2p,  g_B2);
    cudaGetSymbolAddress((void**)&QSp,  g_QSbig);
    cudaGetSymbolAddress((void**)&WqBp, g_WqB);
    cudaGetSymbolAddress((void**)&WoBp, g_WoB);
    cudaGetSymbolAddress((void**)&Fp,   g_Fbig);

    static bool attr_done = false;
    cudaFuncSetAttribute(hmma_fused_v2_kernel,
                         cudaFuncAttributeMaxDynamicSharedMemorySize, K3_SMEM);
    (void)attr_done;

    dim3 blk(256);

    // operand preprocessing
    split2_kernel<<<dim3((TOK   * EDIM) / 256), blk>>>(value, A2p);
    split2_kernel<<<dim3((ERDIM * EDIM) / 256), blk>>>(Wv, B2p);
    split_kernel<0><<<dim3((TOK  * EDIM) / 256), blk>>>(query, QSp);
    split_kernel<1><<<dim3((EDIM * EDIM) / 256), blk>>>(Wq, WqBp);
    split_kernel<1><<<dim3((EDIM * EDIM) / 256), blk>>>(Wo, WoBp);
    prep_iw2_kernel<<<dim3((HNUM * RNUM * DDIM + 255) / 256), blk>>>(rw);

    // K1: q projection (scaled) via HMMA
    hmma_gemm_bias_kernel<<<dim3(EDIM / 128, TOK / 128), blk>>>(
        QSp, WqBp, bq, Qp, 0.125f);

    // K2: fuzzy rule attention
    attn_kernel<<<dim3(TOK), blk>>>(rk);

    // K3: fused v-GEMM + rule reduction, hi/lo-plane scheme
    hmma_fused_v2_kernel<<<dim3(ERDIM / K3_TN, TOK / K3_TM), dim3(512), K3_SMEM>>>(bv);

    // K4: output projection via HMMA
    hmma_gemm_bias_kernel<<<dim3(EDIM / 128, TOK / 128), blk>>>(
        Fp, WoBp, bo, out, 1.0f);
}

// round 7
// speedup vs baseline: 3.1533x; 1.1932x over previous
#include <cuda_runtime.h>
#include <cuda_bf16.h>
#include <cuda_fp16.h>
#include <cstdint>

// Problem constants (fixed by setup_inputs)
#define BATCH 4
#define SEQ   2048
#define EDIM  512
#define HNUM  8
#define RNUM  16
#define DDIM  64
#define TOK   (BATCH * SEQ)      // 8192 tokens
#define ERDIM (EDIM * RNUM)      // 8192 Wv rows

// K1/K4 (bf16 [hi|hi|lo] concat path, proven)
#define KBIG  1536
#define BKC   32
#define NCHUNK (KBIG / BKC)      // 48
#define ROWB  80
#define TILEB (128 * ROWB)

// K3 (fp16 2-product path)
#define K3_TM   256
#define K3_TN   128
#define K3_NCH  16               // 512 / 32
#define RX      144              // A row pitch: 64B hi + 64B lo + 16B pad
#define RB      80               // B row pitch: 64B + 16B pad
#define K3_AT   (K3_TM * RX)     // 36864
#define K3_BT   (K3_TN * RB)     // 10240
#define K3_STAGE (K3_AT + K3_BT) // 47104
#define K3_SMEM (2 * K3_STAGE)   // 94208

// Scratch (allocation-free: __device__ globals)
__device__ float g_Q[TOK * EDIM];              // scaled query projection
__device__ float g_attn[TOK * HNUM * RNUM];    // softmax over rules
__device__ float g_iw2[HNUM * RNUM * DDIM];    // 1 / rules_widths^2
__device__ __half g_A2h[(size_t)TOK   * 1024]; // value row: fp16 [hi(512)|lo(512)]
__device__ __half g_B2h[(size_t)ERDIM * 512];  // Wv row: fp16 single plane
__device__ __nv_bfloat16 g_QSbig[(size_t)TOK * KBIG]; // query  split [hi|hi|lo]
__device__ __nv_bfloat16 g_WqB[(size_t)EDIM  * KBIG]; // Wq     split [hi|lo|hi]
__device__ __nv_bfloat16 g_WoB[(size_t)EDIM  * KBIG]; // Wo     split [hi|lo|hi]
__device__ __nv_bfloat16 g_Fbig[(size_t)TOK  * KBIG]; // F      split [hi|hi|lo], (b,h,s,d) rows

// ---------------------------------------------------------------------------
// Portable PTX helpers (sm_80+)
// ---------------------------------------------------------------------------
__device__ __forceinline__ uint32_t smem_u32(const void* p) {
    uint32_t a;
    asm("{ .reg .u64 t; cvta.to.shared.u64 t, %1; cvt.u32.u64 %0, t; }"
        : "=r"(a) : "l"(p));
    return a;
}
__device__ __forceinline__ void cp_async16(uint32_t dst, const void* src) {
    asm volatile("cp.async.cg.shared.global [%0], [%1], 16;"
                 :: "r"(dst), "l"(src) : "memory");
}
__device__ __forceinline__ void ldmatrix_x4(uint32_t* r, uint32_t addr) {
    asm volatile("ldmatrix.sync.aligned.m8n8.x4.shared.b16 {%0,%1,%2,%3}, [%4];"
                 : "=r"(r[0]), "=r"(r[1]), "=r"(r[2]), "=r"(r[3]) : "r"(addr));
}
__device__ __forceinline__ void mma_bf16(float* c, const uint32_t* a,
                                         uint32_t b0, uint32_t b1) {
    asm volatile(
        "mma.sync.aligned.m16n8k16.row.col.f32.bf16.bf16.f32 "
        "{%0,%1,%2,%3}, {%4,%5,%6,%7}, {%8,%9}, {%0,%1,%2,%3};"
        : "+f"(c[0]), "+f"(c[1]), "+f"(c[2]), "+f"(c[3])
        : "r"(a[0]), "r"(a[1]), "r"(a[2]), "r"(a[3]), "r"(b0), "r"(b1));
}
__device__ __forceinline__ void mma_fp16(float* c, const uint32_t* a,
                                         uint32_t b0, uint32_t b1) {
    asm volatile(
        "mma.sync.aligned.m16n8k16.row.col.f32.f16.f16.f32 "
        "{%0,%1,%2,%3}, {%4,%5,%6,%7}, {%8,%9}, {%0,%1,%2,%3};"
        : "+f"(c[0]), "+f"(c[1]), "+f"(c[2]), "+f"(c[3])
        : "r"(a[0]), "r"(a[1]), "r"(a[2]), "r"(a[3]), "r"(b0), "r"(b1));
}

// ---------------------------------------------------------------------------
// Preprocessing kernels
// ---------------------------------------------------------------------------
// bf16 3-plane splits for K1/K4 (proven path)
template <int MODE>
__global__ __launch_bounds__(256) void split_kernel(
    const float* __restrict__ src, __nv_bfloat16* __restrict__ dst)
{
    size_t i = (size_t)blockIdx.x * 256 + threadIdx.x;
    int row = (int)(i >> 9);
    int k   = (int)(i & 511);
    float v = src[i];
    __nv_bfloat16 hi = __float2bfloat16(v);
    __nv_bfloat16 lo = __float2bfloat16(v - __bfloat162float(hi));
    __nv_bfloat16* d = dst + (size_t)row * KBIG;
    d[k] = hi;
    if (MODE == 0) { d[512 + k] = hi; d[1024 + k] = lo; }
    else           { d[512 + k] = lo; d[1024 + k] = hi; }
}

// fp16 hi/lo 2-plane split (value). float4 per thread, half2 writes.
__global__ __launch_bounds__(256) void split2h_kernel(
    const float* __restrict__ src, __half* __restrict__ dst)
{
    size_t i = (size_t)blockIdx.x * 256 + threadIdx.x;   // over rows * 128 float4
    int row = (int)(i >> 7);
    int k4  = (int)(i & 127) * 4;
    float4 v = ((const float4*)src)[i];
    __half h0 = __float2half_rn(v.x), h1 = __float2half_rn(v.y);
    __half h2 = __float2half_rn(v.z), h3 = __float2half_rn(v.w);
    __half l0 = __float2half_rn(v.x - __half2float(h0));
    __half l1 = __float2half_rn(v.y - __half2float(h1));
    __half l2 = __float2half_rn(v.z - __half2float(h2));
    __half l3 = __float2half_rn(v.w - __half2float(h3));
    __half* d = dst + (size_t)row * 1024;
    *(__half2*)(d + k4)           = __halves2half2(h0, h1);
    *(__half2*)(d + k4 + 2)       = __halves2half2(h2, h3);
    *(__half2*)(d + 512 + k4)     = __halves2half2(l0, l1);
    *(__half2*)(d + 512 + k4 + 2) = __halves2half2(l2, l3);
}

// plain fp32 -> fp16 convert (Wv)
__global__ __launch_bounds__(256) void convh_kernel(
    const float* __restrict__ src, __half* __restrict__ dst)
{
    size_t i = (size_t)blockIdx.x * 256 + threadIdx.x;   // over total/4 float4
    float4 v = ((const float4*)src)[i];
    __half2 a = __halves2half2(__float2half_rn(v.x), __float2half_rn(v.y));
    __half2 b = __halves2half2(__float2half_rn(v.z), __float2half_rn(v.w));
    *(__half2*)(dst + i * 4)     = a;
    *(__half2*)(dst + i * 4 + 2) = b;
}

__global__ __launch_bounds__(256) void prep_iw2_kernel(const float* __restrict__ rw)
{
    int i = blockIdx.x * 256 + threadIdx.x;
    if (i < HNUM * RNUM * DDIM) {
        float t = 1.0f / rw[i];
        g_iw2[i] = t * t;
    }
}

// ---------------------------------------------------------------------------
// K2: fuzzy rule attention. One warp per (token, head); all 32 lanes active.
// ---------------------------------------------------------------------------
__global__ __launch_bounds__(256) void attn_kernel(const float* __restrict__ rk)
{
    __shared__ float qs[EDIM];
    const int token = blockIdx.x;
    {
        const float4* src = (const float4*)(g_Q + (size_t)token * EDIM);
        float4* dst = (float4*)qs;
        if (threadIdx.x < 128) dst[threadIdx.x] = src[threadIdx.x];
    }
    __syncthreads();

    const int h    = threadIdx.x >> 5;
    const int lane = threadIdx.x & 31;

    const float qa = qs[h * DDIM + lane];
    const float qb = qs[h * DDIM + lane + 32];

    float z = 0.f;
    #pragma unroll
    for (int r = 0; r < RNUM; r++) {
        const float* rp = rk    + (size_t)(h * RNUM + r) * DDIM;
        const float* wp = g_iw2 + (size_t)(h * RNUM + r) * DDIM;
        float d0 = qa - rp[lane];
        float d1 = qb - rp[lane + 32];
        float s  = d0 * d0 * wp[lane] + d1 * d1 * wp[lane + 32];
        #pragma unroll
        for (int o = 16; o; o >>= 1) s += __shfl_xor_sync(0xffffffffu, s, o);
        if (lane == r) z = s;
    }

    if (lane < 16) {
        z *= -0.5f / DDIM;
        float m = z;
        #pragma unroll
        for (int o = 8; o; o >>= 1) m = fmaxf(m, __shfl_xor_sync(0x0000ffffu, m, o));
        float e = expf(z - m);
        float sum = e;
        #pragma unroll
        for (int o = 8; o; o >>= 1) sum += __shfl_xor_sync(0x0000ffffu, sum, o);
        g_attn[(size_t)token * (HNUM * RNUM) + h * RNUM + lane] = e / sum;
    }
}

// ---------------------------------------------------------------------------
// K1/K4: bf16 HMMA split-GEMM over K'=1536, tile 128x128, double-buffered.
// ---------------------------------------------------------------------------
__global__ __launch_bounds__(256) void hmma_gemm_bias_kernel(
    const __nv_bfloat16* __restrict__ A, const __nv_bfloat16* __restrict__ B,
    const float* __restrict__ bias, float* __restrict__ C, float scale)
{
    __shared__ __align__(16) char smem[4 * TILEB];
    const uint32_t sbase = smem_u32(smem);

    const int tid    = threadIdx.x;
    const int lane   = tid & 31;
    const int wid    = tid >> 5;
    const int warp_m = wid & 1;
    const int warp_n = wid >> 1;
    const int m0     = blockIdx.y * 128;
    const int n0     = blockIdx.x * 128;

    const int lrow = tid >> 2;
    const int lc16 = tid & 3;

    float acc[4][4][4] = {};

    auto load_chunk = [&](int c, int buf) {
        const uint32_t a_s = sbase + (uint32_t)buf * TILEB;
        const uint32_t b_s = sbase + 2u * TILEB + (uint32_t)buf * TILEB;
        #pragma unroll
        for (int t = 0; t < 2; t++) {
            const int row = lrow + t * 64;
            const uint32_t so = (uint32_t)row * ROWB + (uint32_t)lc16 * 16;
            cp_async16(a_s + so, A + (size_t)(m0 + row) * KBIG + c * BKC + lc16 * 8);
            cp_async16(b_s + so, B + (size_t)(n0 + row) * KBIG + c * BKC + lc16 * 8);
        }
        asm volatile("cp.async.commit_group;" ::: "memory");
    };

    const uint32_t lm_row = (uint32_t)(lane & 15);
    const uint32_t lm_kb  = (uint32_t)(lane >> 4) * 16;

    load_chunk(0, 0);

    for (int c = 0; c < NCHUNK; c++) {
        const int buf = c & 1;
        if (c + 1 < NCHUNK) {
            load_chunk(c + 1, buf ^ 1);
            asm volatile("cp.async.wait_group 1;" ::: "memory");
        } else {
            asm volatile("cp.async.wait_group 0;" ::: "memory");
        }
        __syncthreads();

        const uint32_t a_s = sbase + (uint32_t)buf * TILEB;
        const uint32_t b_s = sbase + 2u * TILEB + (uint32_t)buf * TILEB;

        #pragma unroll
        for (int ks = 0; ks < 2; ks++) {
            const uint32_t kb = (uint32_t)ks * 32 + lm_kb;
            uint32_t afr[4][4];
            #pragma unroll
            for (int mt = 0; mt < 4; mt++) {
                const uint32_t row = (uint32_t)(warp_m * 64 + mt * 16) + lm_row;
                ldmatrix_x4(afr[mt], a_s + row * ROWB + kb);
            }
            uint32_t bfr[2][4];
            #pragma unroll
            for (int np = 0; np < 2; np++) {
                const uint32_t row = (uint32_t)(warp_n * 32 + np * 16) + lm_row;
                ldmatrix_x4(bfr[np], b_s + row * ROWB + kb);
            }
            #pragma unroll
            for (int mt = 0; mt < 4; mt++)
                #pragma unroll
                for (int nt = 0; nt < 4; nt++)
                    mma_bf16(acc[mt][nt], afr[mt],
                             bfr[nt >> 1][nt & 1], bfr[nt >> 1][(nt & 1) + 2]);
        }
        __syncthreads();
    }

    const int q  = lane & 3;
    const int rg = lane >> 2;
    #pragma unroll
    for (int mt = 0; mt < 4; mt++) {
        #pragma unroll
        for (int half = 0; half < 2; half++) {
            const int row = m0 + warp_m * 64 + mt * 16 + rg + half * 8;
            #pragma unroll
            for (int nt = 0; nt < 4; nt++) {
                const int col = n0 + warp_n * 32 + nt * 8 + q * 2;
                float2 v;
                v.x = (acc[mt][nt][half * 2 + 0] + bias[col])     * scale;
                v.y = (acc[mt][nt][half * 2 + 1] + bias[col + 1]) * scale;
                *(float2*)(C + (size_t)row * EDIM + col) = v;
            }
        }
    }
}

// ---------------------------------------------------------------------------
// K3: fp16 2-product split-GEMM + fused fuzzy epilogue.
//   Per 32-K chunk: Ahi,Alo (256x32 fp16) and B (128x32 fp16);
//   acc += Ahi*B + Alo*B  (exact A, B rounded to fp16: rel err ~2.8e-4).
// Tile 256x128, 512 threads (warps 4x4), 2-stage cp.async, 1 sync per chunk.
// Writes g_Fbig [hi|hi|lo] bf16 in (b,h,s,d) row order.
// ---------------------------------------------------------------------------
__global__ void __launch_bounds__(512, 1) hmma_fused_v3_kernel(const float* __restrict__ bv)
{
    extern __shared__ __align__(16) char smem[];
    const uint32_t sbase = smem_u32(smem);

    const int tid    = threadIdx.x;
    const int lane   = tid & 31;
    const int wid    = tid >> 5;
    const int warp_m = wid & 3;     // 4 x 64 rows
    const int warp_n = wid >> 2;    // 4 x 32 cols
    const int m0     = blockIdx.y * K3_TM;   // token base
    const int n0     = blockIdx.x * K3_TN;   // Wv-row base

    float acc[4][4][4] = {};

    auto load_chunk = [&](int c, int buf) {
        const uint32_t s0 = sbase + (uint32_t)buf * K3_STAGE;
        #pragma unroll
        for (int i = 0; i < 4; i++) {        // A: 256 rows x (hi,lo) x 4 x 16B
            const int idx  = tid + i * 512;
            const int row  = idx >> 3;
            const int half = (idx >> 2) & 1;
            const int c16  = idx & 3;
            cp_async16(s0 + (uint32_t)row * RX + (uint32_t)half * 64 + (uint32_t)c16 * 16,
                       g_A2h + (size_t)(m0 + row) * 1024 + half * 512 + c * 32 + c16 * 8);
        }
        {                                     // B: 128 rows x 4 x 16B
            const int row = tid >> 2;
            const int c16 = tid & 3;
            cp_async16(s0 + K3_AT + (uint32_t)row * RB + (uint32_t)c16 * 16,
                       g_B2h + (size_t)(n0 + row) * 512 + c * 32 + c16 * 8);
        }
        asm volatile("cp.async.commit_group;" ::: "memory");
    };

    const uint32_t lm_row = (uint32_t)(lane & 15);
    const uint32_t lm_kb  = (uint32_t)(lane >> 4) * 16;

    load_chunk(0, 0);

    for (int c = 0; c < K3_NCH; c++) {
        asm volatile("cp.async.wait_group 0;" ::: "memory");
        __syncthreads();
        // slot (c+1)&1 was last read in chunk c-1; safe after the sync above.
        if (c + 1 < K3_NCH) load_chunk(c + 1, (c + 1) & 1);

        const uint32_t a_s = sbase + (uint32_t)(c & 1) * K3_STAGE;
        const uint32_t b_s = a_s + K3_AT;

        #pragma unroll
        for (int ks = 0; ks < 2; ks++) {
            const uint32_t kb = (uint32_t)ks * 32 + lm_kb;
            uint32_t afr[4][4];
            uint32_t bfr[2][4];
            #pragma unroll
            for (int np = 0; np < 2; np++) {          // B
                const uint32_t row = (uint32_t)(warp_n * 32 + np * 16) + lm_row;
                ldmatrix_x4(bfr[np], b_s + row * RB + kb);
            }
            #pragma unroll
            for (int mt = 0; mt < 4; mt++) {          // A hi
                const uint32_t row = (uint32_t)(warp_m * 64 + mt * 16) + lm_row;
                ldmatrix_x4(afr[mt], a_s + row * RX + kb);
            }
            #pragma unroll
            for (int mt = 0; mt < 4; mt++)            // P1: Ahi * B
                #pragma unroll
                for (int nt = 0; nt < 4; nt++)
                    mma_fp16(acc[mt][nt], afr[mt],
                             bfr[nt >> 1][nt & 1], bfr[nt >> 1][(nt & 1) + 2]);
            #pragma unroll
            for (int mt = 0; mt < 4; mt++) {          // A lo (reuse afr regs)
                const uint32_t row = (uint32_t)(warp_m * 64 + mt * 16) + lm_row;
                ldmatrix_x4(afr[mt], a_s + row * RX + kb + 64);
            }
            #pragma unroll
            for (int mt = 0; mt < 4; mt++)            // P2: Alo * B
                #pragma unroll
                for (int nt = 0; nt < 4; nt++)
                    mma_fp16(acc[mt][nt], afr[mt],
                             bfr[nt >> 1][nt & 1], bfr[nt >> 1][(nt & 1) + 2]);
        }
    }

    // -------- fused fuzzy epilogue (emits hi/lo bf16 split of F) --------
    const int q   = lane & 3;
    const int rg  = lane >> 2;
    const int hd0 = n0 >> 4;      // first feature of tile (multiple of 8)
    const int h   = hd0 >> 6;
    const int d0c = hd0 & 63;

    float bvv[2][4];
    #pragma unroll
    for (int g = 0; g < 2; g++)
        #pragma unroll
        for (int ntl = 0; ntl < 2; ntl++)
            #pragma unroll
            for (int j = 0; j < 2; j++)
                bvv[g][ntl * 2 + j] =
                    __ldg(bv + n0 + warp_n * 32 + g * 16 + ntl * 8 + q * 2 + j);

    #pragma unroll
    for (int mt = 0; mt < 4; mt++) {
        #pragma unroll
        for (int half = 0; half < 2; half++) {
            const int rowm  = warp_m * 64 + mt * 16 + rg + half * 8;
            const int token = m0 + rowm;
            const int b     = token >> 11;
            const int s     = token & 2047;
            const float* ap = g_attn + (size_t)token * (HNUM * RNUM) + h * RNUM;
            const float at0 = ap[q * 2],     at1 = ap[q * 2 + 1];
            const float at2 = ap[q * 2 + 8], at3 = ap[q * 2 + 9];

            const int frow  = (b * HNUM + h) * 256 + (s >> 3);
            const int cbase = (s & 7) * 64;

            #pragma unroll
            for (int g = 0; g < 2; g++) {
                float p = (acc[mt][g * 2 + 0][half * 2 + 0] + bvv[g][0]) * at0
                        + (acc[mt][g * 2 + 0][half * 2 + 1] + bvv[g][1]) * at1
                        + (acc[mt][g * 2 + 1][half * 2 + 0] + bvv[g][2]) * at2
                        + (acc[mt][g * 2 + 1][half * 2 + 1] + bvv[g][3]) * at3;
                p += __shfl_down_sync(0xffffffffu, p, 2);
                p += __shfl_down_sync(0xffffffffu, p, 1);
                if (q == 0) {
                    p *= 0.125f;  // D^-0.5
                    const int col = cbase + d0c + warp_n * 2 + g;
                    __nv_bfloat16 hi = __float2bfloat16(p);
                    __nv_bfloat16 lo = __float2bfloat16(p - __bfloat162float(hi));
                    __nv_bfloat16* f = g_Fbig + (size_t)frow * KBIG + col;
                    f[0]    = hi;
                    f[512]  = hi;
                    f[1024] = lo;
                }
            }
        }
    }
}

// ---------------------------------------------------------------------------
extern "C" void kernel_launch(void* const* d_in, const int* in_sizes, int n_in,
                              void* d_out, int out_size)
{
    const float* query = (const float*)d_in[0];
    // d_in[1] = key: unused by the reference computation
    const float* value = (const float*)d_in[2];
    const float* Wq    = (const float*)d_in[3];
    const float* bq    = (const float*)d_in[4];
    const float* Wv    = (const float*)d_in[5];
    const float* bv    = (const float*)d_in[6];
    const float* Wo    = (const float*)d_in[7];
    const float* bo    = (const float*)d_in[8];
    const float* rk    = (const float*)d_in[9];
    const float* rw    = (const float*)d_in[10];
    float* out = (float*)d_out;

    float* Qp = nullptr;
    __half *A2p = nullptr, *B2p = nullptr;
    __nv_bfloat16 *QSp = nullptr, *WqBp = nullptr, *WoBp = nullptr, *Fp = nullptr;
    cudaGetSymbolAddress((void**)&Qp,   g_Q);
    cudaGetSymbolAddress((void**)&A2p,  g_A2h);
    cudaGetSymbolAddress((void**)&B2p,  g_B2h);
    cudaGetSymbolAddress((void**)&QSp,  g_QSbig);
    cudaGetSymbolAddress((void**)&WqBp, g_WqB);
    cudaGetSymbolAddress((void**)&WoBp, g_WoB);
    cudaGetSymbolAddress((void**)&Fp,   g_Fbig);

    cudaFuncSetAttribute(hmma_fused_v3_kernel,
                         cudaFuncAttributeMaxDynamicSharedMemorySize, K3_SMEM);

    dim3 blk(256);

    // operand preprocessing
    split2h_kernel<<<dim3((TOK * EDIM) / 1024), blk>>>(value, A2p);     // fp16 hi/lo
    convh_kernel<<<dim3((ERDIM * EDIM) / 1024), blk>>>(Wv, B2p);        // fp16
    split_kernel<0><<<dim3((TOK  * EDIM) / 256), blk>>>(query, QSp);
    split_kernel<1><<<dim3((EDIM * EDIM) / 256), blk>>>(Wq, WqBp);
    split_kernel<1><<<dim3((EDIM * EDIM) / 256), blk>>>(Wo, WoBp);
    prep_iw2_kernel<<<dim3((HNUM * RNUM * DDIM + 255) / 256), blk>>>(rw);

    // K1: q projection (scaled) via bf16 HMMA
    hmma_gemm_bias_kernel<<<dim3(EDIM / 128, TOK / 128), blk>>>(
        QSp, WqBp, bq, Qp, 0.125f);

    // K2: fuzzy rule attention
    attn_kernel<<<dim3(TOK), blk>>>(rk);

    // K3: fused v-GEMM + rule reduction, fp16 2-product scheme
    hmma_fused_v3_kernel<<<dim3(ERDIM / K3_TN, TOK / K3_TM), dim3(512), K3_SMEM>>>(bv);

    // K4: output projection via bf16 HMMA
    hmma_gemm_bias_kernel<<<dim3(EDIM / 128, TOK / 128), blk>>>(
        Fp, WoBp, bo, out, 1.0f);
}

// round 8
// speedup vs baseline: 3.1600x; 1.0021x over previous
#include <cuda_runtime.h>
#include <cuda_bf16.h>
#include <cuda_fp16.h>
#include <cstdint>

// Problem constants (fixed by setup_inputs)
#define BATCH 4
#define SEQ   2048
#define EDIM  512
#define HNUM  8
#define RNUM  16
#define DDIM  64
#define TOK   (BATCH * SEQ)      // 8192 tokens
#define ERDIM (EDIM * RNUM)      // 8192 Wv rows

// K1/K4 (bf16 [hi|hi|lo] concat path, proven)
#define KBIG  1536
#define BKC   32
#define NCHUNK (KBIG / BKC)      // 48
#define ROWB  80
#define TILEB (128 * ROWB)

// K3 (fp16 2-product path)
#define K3_TM   256
#define K3_TN   128
#define K3_NCH  16               // 512 / 32
#define RX      144              // A row pitch: 64B hi + 64B lo + 16B pad
#define RB      80               // B row pitch: 64B + 16B pad
#define K3_AT   (K3_TM * RX)     // 36864
#define K3_BT   (K3_TN * RB)     // 10240
#define K3_STAGE (K3_AT + K3_BT) // 47104
#define K3_SMEM (2 * K3_STAGE)   // 94208

// Scratch (allocation-free: __device__ globals)
__device__ float g_Q[TOK * EDIM];              // scaled query projection
__device__ float g_attn[TOK * HNUM * RNUM];    // softmax over rules
__device__ float g_iw2[HNUM * RNUM * DDIM];    // 1 / rules_widths^2
__device__ __half g_A2h[(size_t)TOK   * 1024]; // value row: fp16 [hi(512)|lo(512)]
__device__ __half g_B2h[(size_t)ERDIM * 512];  // Wv row: fp16 single plane
__device__ __nv_bfloat16 g_QSbig[(size_t)TOK * KBIG]; // query  split [hi|hi|lo]
__device__ __nv_bfloat16 g_WqB[(size_t)EDIM  * KBIG]; // Wq     split [hi|lo|hi]
__device__ __nv_bfloat16 g_WoB[(size_t)EDIM  * KBIG]; // Wo     split [hi|lo|hi]
__device__ __nv_bfloat16 g_Fbig[(size_t)TOK  * KBIG]; // F      split [hi|hi|lo], (b,h,s,d) rows

// ---------------------------------------------------------------------------
// Portable PTX helpers (sm_80+)
// ---------------------------------------------------------------------------
__device__ __forceinline__ uint32_t smem_u32(const void* p) {
    uint32_t a;
    asm("{ .reg .u64 t; cvta.to.shared.u64 t, %1; cvt.u32.u64 %0, t; }"
        : "=r"(a) : "l"(p));
    return a;
}
__device__ __forceinline__ void cp_async16(uint32_t dst, const void* src) {
    asm volatile("cp.async.cg.shared.global [%0], [%1], 16;"
                 :: "r"(dst), "l"(src) : "memory");
}
__device__ __forceinline__ void ldmatrix_x4(uint32_t* r, uint32_t addr) {
    asm volatile("ldmatrix.sync.aligned.m8n8.x4.shared.b16 {%0,%1,%2,%3}, [%4];"
                 : "=r"(r[0]), "=r"(r[1]), "=r"(r[2]), "=r"(r[3]) : "r"(addr));
}
__device__ __forceinline__ void mma_bf16(float* c, const uint32_t* a,
                                         uint32_t b0, uint32_t b1) {
    asm volatile(
        "mma.sync.aligned.m16n8k16.row.col.f32.bf16.bf16.f32 "
        "{%0,%1,%2,%3}, {%4,%5,%6,%7}, {%8,%9}, {%0,%1,%2,%3};"
        : "+f"(c[0]), "+f"(c[1]), "+f"(c[2]), "+f"(c[3])
        : "r"(a[0]), "r"(a[1]), "r"(a[2]), "r"(a[3]), "r"(b0), "r"(b1));
}
__device__ __forceinline__ void mma_fp16(float* c, const uint32_t* a,
                                         uint32_t b0, uint32_t b1) {
    asm volatile(
        "mma.sync.aligned.m16n8k16.row.col.f32.f16.f16.f32 "
        "{%0,%1,%2,%3}, {%4,%5,%6,%7}, {%8,%9}, {%0,%1,%2,%3};"
        : "+f"(c[0]), "+f"(c[1]), "+f"(c[2]), "+f"(c[3])
        : "r"(a[0]), "r"(a[1]), "r"(a[2]), "r"(a[3]), "r"(b0), "r"(b1));
}

// ---------------------------------------------------------------------------
// Preprocessing kernels
// ---------------------------------------------------------------------------
// bf16 3-plane splits for K1/K4 (proven path)
template <int MODE>
__global__ __launch_bounds__(256) void split_kernel(
    const float* __restrict__ src, __nv_bfloat16* __restrict__ dst)
{
    size_t i = (size_t)blockIdx.x * 256 + threadIdx.x;
    int row = (int)(i >> 9);
    int k   = (int)(i & 511);
    float v = src[i];
    __nv_bfloat16 hi = __float2bfloat16(v);
    __nv_bfloat16 lo = __float2bfloat16(v - __bfloat162float(hi));
    __nv_bfloat16* d = dst + (size_t)row * KBIG;
    d[k] = hi;
    if (MODE == 0) { d[512 + k] = hi; d[1024 + k] = lo; }
    else           { d[512 + k] = lo; d[1024 + k] = hi; }
}

// fp16 hi/lo 2-plane split (value). float4 per thread, half2 writes.
__global__ __launch_bounds__(256) void split2h_kernel(
    const float* __restrict__ src, __half* __restrict__ dst)
{
    size_t i = (size_t)blockIdx.x * 256 + threadIdx.x;   // over rows * 128 float4
    int row = (int)(i >> 7);
    int k4  = (int)(i & 127) * 4;
    float4 v = ((const float4*)src)[i];
    __half h0 = __float2half_rn(v.x), h1 = __float2half_rn(v.y);
    __half h2 = __float2half_rn(v.z), h3 = __float2half_rn(v.w);
    __half l0 = __float2half_rn(v.x - __half2float(h0));
    __half l1 = __float2half_rn(v.y - __half2float(h1));
    __half l2 = __float2half_rn(v.z - __half2float(h2));
    __half l3 = __float2half_rn(v.w - __half2float(h3));
    __half* d = dst + (size_t)row * 1024;
    *(__half2*)(d + k4)           = __halves2half2(h0, h1);
    *(__half2*)(d + k4 + 2)       = __halves2half2(h2, h3);
    *(__half2*)(d + 512 + k4)     = __halves2half2(l0, l1);
    *(__half2*)(d + 512 + k4 + 2) = __halves2half2(l2, l3);
}

// plain fp32 -> fp16 convert (Wv)
__global__ __launch_bounds__(256) void convh_kernel(
    const float* __restrict__ src, __half* __restrict__ dst)
{
    size_t i = (size_t)blockIdx.x * 256 + threadIdx.x;   // over total/4 float4
    float4 v = ((const float4*)src)[i];
    __half2 a = __halves2half2(__float2half_rn(v.x), __float2half_rn(v.y));
    __half2 b = __halves2half2(__float2half_rn(v.z), __float2half_rn(v.w));
    *(__half2*)(dst + i * 4)     = a;
    *(__half2*)(dst + i * 4 + 2) = b;
}

__global__ __launch_bounds__(256) void prep_iw2_kernel(const float* __restrict__ rw)
{
    int i = blockIdx.x * 256 + threadIdx.x;
    if (i < HNUM * RNUM * DDIM) {
        float t = 1.0f / rw[i];
        g_iw2[i] = t * t;
    }
}

// ---------------------------------------------------------------------------
// K2: fuzzy rule attention. One warp per (token, head); all 32 lanes active.
// ---------------------------------------------------------------------------
__global__ __launch_bounds__(256) void attn_kernel(const float* __restrict__ rk)
{
    __shared__ float qs[EDIM];
    const int token = blockIdx.x;
    {
        const float4* src = (const float4*)(g_Q + (size_t)token * EDIM);
        float4* dst = (float4*)qs;
        if (threadIdx.x < 128) dst[threadIdx.x] = src[threadIdx.x];
    }
    __syncthreads();

    const int h    = threadIdx.x >> 5;
    const int lane = threadIdx.x & 31;

    const float qa = qs[h * DDIM + lane];
    const float qb = qs[h * DDIM + lane + 32];

    float z = 0.f;
    #pragma unroll
    for (int r = 0; r < RNUM; r++) {
        const float* rp = rk    + (size_t)(h * RNUM + r) * DDIM;
        const float* wp = g_iw2 + (size_t)(h * RNUM + r) * DDIM;
        float d0 = qa - rp[lane];
        float d1 = qb - rp[lane + 32];
        float s  = d0 * d0 * wp[lane] + d1 * d1 * wp[lane + 32];
        #pragma unroll
        for (int o = 16; o; o >>= 1) s += __shfl_xor_sync(0xffffffffu, s, o);
        if (lane == r) z = s;
    }

    if (lane < 16) {
        z *= -0.5f / DDIM;
        float m = z;
        #pragma unroll
        for (int o = 8; o; o >>= 1) m = fmaxf(m, __shfl_xor_sync(0x0000ffffu, m, o));
        float e = expf(z - m);
        float sum = e;
        #pragma unroll
        for (int o = 8; o; o >>= 1) sum += __shfl_xor_sync(0x0000ffffu, sum, o);
        g_attn[(size_t)token * (HNUM * RNUM) + h * RNUM + lane] = e / sum;
    }
}

// ---------------------------------------------------------------------------
// K1/K4: bf16 HMMA split-GEMM over K'=1536, tile 128x128, double-buffered.
// ---------------------------------------------------------------------------
__global__ __launch_bounds__(256) void hmma_gemm_bias_kernel(
    const __nv_bfloat16* __restrict__ A, const __nv_bfloat16* __restrict__ B,
    const float* __restrict__ bias, float* __restrict__ C, float scale)
{
    __shared__ __align__(16) char smem[4 * TILEB];
    const uint32_t sbase = smem_u32(smem);

    const int tid    = threadIdx.x;
    const int lane   = tid & 31;
    const int wid    = tid >> 5;
    const int warp_m = wid & 1;
    const int warp_n = wid >> 1;
    const int m0     = blockIdx.y * 128;
    const int n0     = blockIdx.x * 128;

    const int lrow = tid >> 2;
    const int lc16 = tid & 3;

    float acc[4][4][4] = {};

    auto load_chunk = [&](int c, int buf) {
        const uint32_t a_s = sbase + (uint32_t)buf * TILEB;
        const uint32_t b_s = sbase + 2u * TILEB + (uint32_t)buf * TILEB;
        #pragma unroll
        for (int t = 0; t < 2; t++) {
            const int row = lrow + t * 64;
            const uint32_t so = (uint32_t)row * ROWB + (uint32_t)lc16 * 16;
            cp_async16(a_s + so, A + (size_t)(m0 + row) * KBIG + c * BKC + lc16 * 8);
            cp_async16(b_s + so, B + (size_t)(n0 + row) * KBIG + c * BKC + lc16 * 8);
        }
        asm volatile("cp.async.commit_group;" ::: "memory");
    };

    const uint32_t lm_row = (uint32_t)(lane & 15);
    const uint32_t lm_kb  = (uint32_t)(lane >> 4) * 16;

    load_chunk(0, 0);

    for (int c = 0; c < NCHUNK; c++) {
        const int buf = c & 1;
        if (c + 1 < NCHUNK) {
            load_chunk(c + 1, buf ^ 1);
            asm volatile("cp.async.wait_group 1;" ::: "memory");
        } else {
            asm volatile("cp.async.wait_group 0;" ::: "memory");
        }
        __syncthreads();

        const uint32_t a_s = sbase + (uint32_t)buf * TILEB;
        const uint32_t b_s = sbase + 2u * TILEB + (uint32_t)buf * TILEB;

        #pragma unroll
        for (int ks = 0; ks < 2; ks++) {
            const uint32_t kb = (uint32_t)ks * 32 + lm_kb;
            uint32_t afr[4][4];
            #pragma unroll
            for (int mt = 0; mt < 4; mt++) {
                const uint32_t row = (uint32_t)(warp_m * 64 + mt * 16) + lm_row;
                ldmatrix_x4(afr[mt], a_s + row * ROWB + kb);
            }
            uint32_t bfr[2][4];
            #pragma unroll
            for (int np = 0; np < 2; np++) {
                const uint32_t row = (uint32_t)(warp_n * 32 + np * 16) + lm_row;
                ldmatrix_x4(bfr[np], b_s + row * ROWB + kb);
            }
            #pragma unroll
            for (int mt = 0; mt < 4; mt++)
                #pragma unroll
                for (int nt = 0; nt < 4; nt++)
                    mma_bf16(acc[mt][nt], afr[mt],
                             bfr[nt >> 1][nt & 1], bfr[nt >> 1][(nt & 1) + 2]);
        }
        __syncthreads();
    }

    const int q  = lane & 3;
    const int rg = lane >> 2;
    #pragma unroll
    for (int mt = 0; mt < 4; mt++) {
        #pragma unroll
        for (int half = 0; half < 2; half++) {
            const int row = m0 + warp_m * 64 + mt * 16 + rg + half * 8;
            #pragma unroll
            for (int nt = 0; nt < 4; nt++) {
                const int col = n0 + warp_n * 32 + nt * 8 + q * 2;
                float2 v;
                v.x = (acc[mt][nt][half * 2 + 0] + bias[col])     * scale;
                v.y = (acc[mt][nt][half * 2 + 1] + bias[col + 1]) * scale;
                *(float2*)(C + (size_t)row * EDIM + col) = v;
            }
        }
    }
}

// ---------------------------------------------------------------------------
// K3: fp16 2-product split-GEMM + fused fuzzy epilogue.
//   Per 32-K chunk: Ahi,Alo (256x32 fp16) and B (128x32 fp16);
//   acc += Ahi*B + Alo*B  (exact A, B rounded to fp16: rel err ~2.8e-4).
// Tile 256x128, 512 threads (warps 4x4), 2-stage cp.async, 1 sync per chunk.
// Writes g_Fbig [hi|hi|lo] bf16 in (b,h,s,d) row order.
// ---------------------------------------------------------------------------
__global__ void __launch_bounds__(512, 1) hmma_fused_v3_kernel(const float* __restrict__ bv)
{
    extern __shared__ __align__(16) char smem[];
    const uint32_t sbase = smem_u32(smem);

    const int tid    = threadIdx.x;
    const int lane   = tid & 31;
    const int wid    = tid >> 5;
    const int warp_m = wid & 3;     // 4 x 64 rows
    const int warp_n = wid >> 2;    // 4 x 32 cols
    const int m0     = blockIdx.y * K3_TM;   // token base
    const int n0     = blockIdx.x * K3_TN;   // Wv-row base

    float acc[4][4][4] = {};

    auto load_chunk = [&](int c, int buf) {
        const uint32_t s0 = sbase + (uint32_t)buf * K3_STAGE;
        #pragma unroll
        for (int i = 0; i < 4; i++) {        // A: 256 rows x (hi,lo) x 4 x 16B
            const int idx  = tid + i * 512;
            const int row  = idx >> 3;
            const int half = (idx >> 2) & 1;
            const int c16  = idx & 3;
            cp_async16(s0 + (uint32_t)row * RX + (uint32_t)half * 64 + (uint32_t)c16 * 16,
                       g_A2h + (size_t)(m0 + row) * 1024 + half * 512 + c * 32 + c16 * 8);
        }
        {                                     // B: 128 rows x 4 x 16B
            const int row = tid >> 2;
            const int c16 = tid & 3;
            cp_async16(s0 + K3_AT + (uint32_t)row * RB + (uint32_t)c16 * 16,
                       g_B2h + (size_t)(n0 + row) * 512 + c * 32 + c16 * 8);
        }
        asm volatile("cp.async.commit_group;" ::: "memory");
    };

    const uint32_t lm_row = (uint32_t)(lane & 15);
    const uint32_t lm_kb  = (uint32_t)(lane >> 4) * 16;

    load_chunk(0, 0);

    for (int c = 0; c < K3_NCH; c++) {
        asm volatile("cp.async.wait_group 0;" ::: "memory");
        __syncthreads();
        // slot (c+1)&1 was last read in chunk c-1; safe after the sync above.
        if (c + 1 < K3_NCH) load_chunk(c + 1, (c + 1) & 1);

        const uint32_t a_s = sbase + (uint32_t)(c & 1) * K3_STAGE;
        const uint32_t b_s = a_s + K3_AT;

        #pragma unroll
        for (int ks = 0; ks < 2; ks++) {
            const uint32_t kb = (uint32_t)ks * 32 + lm_kb;
            uint32_t afr[4][4];
            uint32_t bfr[2][4];
            #pragma unroll
            for (int np = 0; np < 2; np++) {          // B
                const uint32_t row = (uint32_t)(warp_n * 32 + np * 16) + lm_row;
                ldmatrix_x4(bfr[np], b_s + row * RB + kb);
            }
            #pragma unroll
            for (int mt = 0; mt < 4; mt++) {          // A hi
                const uint32_t row = (uint32_t)(warp_m * 64 + mt * 16) + lm_row;
                ldmatrix_x4(afr[mt], a_s + row * RX + kb);
            }
            #pragma unroll
            for (int mt = 0; mt < 4; mt++)            // P1: Ahi * B
                #pragma unroll
                for (int nt = 0; nt < 4; nt++)
                    mma_fp16(acc[mt][nt], afr[mt],
                             bfr[nt >> 1][nt & 1], bfr[nt >> 1][(nt & 1) + 2]);
            #pragma unroll
            for (int mt = 0; mt < 4; mt++) {          // A lo (reuse afr regs)
                const uint32_t row = (uint32_t)(warp_m * 64 + mt * 16) + lm_row;
                ldmatrix_x4(afr[mt], a_s + row * RX + kb + 64);
            }
            #pragma unroll
            for (int mt = 0; mt < 4; mt++)            // P2: Alo * B
                #pragma unroll
                for (int nt = 0; nt < 4; nt++)
                    mma_fp16(acc[mt][nt], afr[mt],
                             bfr[nt >> 1][nt & 1], bfr[nt >> 1][(nt & 1) + 2]);
        }
    }

    // -------- fused fuzzy epilogue (emits hi/lo bf16 split of F) --------
    const int q   = lane & 3;
    const int rg  = lane >> 2;
    const int hd0 = n0 >> 4;      // first feature of tile (multiple of 8)
    const int h   = hd0 >> 6;
    const int d0c = hd0 & 63;

    float bvv[2][4];
    #pragma unroll
    for (int g = 0; g < 2; g++)
        #pragma unroll
        for (int ntl = 0; ntl < 2; ntl++)
            #pragma unroll
            for (int j = 0; j < 2; j++)
                bvv[g][ntl * 2 + j] =
                    __ldg(bv + n0 + warp_n * 32 + g * 16 + ntl * 8 + q * 2 + j);

    #pragma unroll
    for (int mt = 0; mt < 4; mt++) {
        #pragma unroll
        for (int half = 0; half < 2; half++) {
            const int rowm  = warp_m * 64 + mt * 16 + rg + half * 8;
            const int token = m0 + rowm;
            const int b     = token >> 11;
            const int s     = token & 2047;
            const float* ap = g_attn + (size_t)token * (HNUM * RNUM) + h * RNUM;
            const float at0 = ap[q * 2],     at1 = ap[q * 2 + 1];
            const float at2 = ap[q * 2 + 8], at3 = ap[q * 2 + 9];

            const int frow  = (b * HNUM + h) * 256 + (s >> 3);
            const int cbase = (s & 7) * 64;

            #pragma unroll
            for (int g = 0; g < 2; g++) {
                float p = (acc[mt][g * 2 + 0][half * 2 + 0] + bvv[g][0]) * at0
                        + (acc[mt][g * 2 + 0][half * 2 + 1] + bvv[g][1]) * at1
                        + (acc[mt][g * 2 + 1][half * 2 + 0] + bvv[g][2]) * at2
                        + (acc[mt][g * 2 + 1][half * 2 + 1] + bvv[g][3]) * at3;
                p += __shfl_down_sync(0xffffffffu, p, 2);
                p += __shfl_down_sync(0xffffffffu, p, 1);
                if (q == 0) {
                    p *= 0.125f;  // D^-0.5
                    const int col = cbase + d0c + warp_n * 2 + g;
                    __nv_bfloat16 hi = __float2bfloat16(p);
                    __nv_bfloat16 lo = __float2bfloat16(p - __bfloat162float(hi));
                    __nv_bfloat16* f = g_Fbig + (size_t)frow * KBIG + col;
                    f[0]    = hi;
                    f[512]  = hi;
                    f[1024] = lo;
                }
            }
        }
    }
}

// ---------------------------------------------------------------------------
extern "C" void kernel_launch(void* const* d_in, const int* in_sizes, int n_in,
                              void* d_out, int out_size)
{
    const float* query = (const float*)d_in[0];
    // d_in[1] = key: unused by the reference computation
    const float* value = (const float*)d_in[2];
    const float* Wq    = (const float*)d_in[3];
    const float* bq    = (const float*)d_in[4];
    const float* Wv    = (const float*)d_in[5];
    const float* bv    = (const float*)d_in[6];
    const float* Wo    = (const float*)d_in[7];
    const float* bo    = (const float*)d_in[8];
    const float* rk    = (const float*)d_in[9];
    const float* rw    = (const float*)d_in[10];
    float* out = (float*)d_out;

    float* Qp = nullptr;
    __half *A2p = nullptr, *B2p = nullptr;
    __nv_bfloat16 *QSp = nullptr, *WqBp = nullptr, *WoBp = nullptr, *Fp = nullptr;
    cudaGetSymbolAddress((void**)&Qp,   g_Q);
    cudaGetSymbolAddress((void**)&A2p,  g_A2h);
    cudaGetSymbolAddress((void**)&B2p,  g_B2h);
    cudaGetSymbolAddress((void**)&QSp,  g_QSbig);
    cudaGetSymbolAddress((void**)&WqBp, g_WqB);
    cudaGetSymbolAddress((void**)&WoBp, g_WoB);
    cudaGetSymbolAddress((void**)&Fp,   g_Fbig);

    cudaFuncSetAttribute(hmma_fused_v3_kernel,
                         cudaFuncAttributeMaxDynamicSharedMemorySize, K3_SMEM);

    dim3 blk(256);

    // operand preprocessing
    split2h_kernel<<<dim3((TOK * EDIM) / 1024), blk>>>(value, A2p);     // fp16 hi/lo
    convh_kernel<<<dim3((ERDIM * EDIM) / 1024), blk>>>(Wv, B2p);        // fp16
    split_kernel<0><<<dim3((TOK  * EDIM) / 256), blk>>>(query, QSp);
    split_kernel<1><<<dim3((EDIM * EDIM) / 256), blk>>>(Wq, WqBp);
    split_kernel<1><<<dim3((EDIM * EDIM) / 256), blk>>>(Wo, WoBp);
    prep_iw2_kernel<<<dim3((HNUM * RNUM * DDIM + 255) / 256), blk>>>(rw);

    // K1: q projection (scaled) via bf16 HMMA
    hmma_gemm_bias_kernel<<<dim3(EDIM / 128, TOK / 128), blk>>>(
        QSp, WqBp, bq, Qp, 0.125f);

    // K2: fuzzy rule attention
    attn_kernel<<<dim3(TOK), blk>>>(rk);

    // K3: fused v-GEMM + rule reduction, fp16 2-product scheme
    hmma_fused_v3_kernel<<<dim3(ERDIM / K3_TN, TOK / K3_TM), dim3(512), K3_SMEM>>>(bv);

    // K4: output projection via bf16 HMMA
    hmma_gemm_bias_kernel<<<dim3(EDIM / 128, TOK / 128), blk>>>(
        Fp, WoBp, bo, out, 1.0f);
}